// round 4
// baseline (speedup 1.0000x reference)
#include <cuda_runtime.h>
#include <math.h>

#define NB   128
#define CIN  128
#define TIN  2500
#define CO   64
#define KW   27
#define TOUT 625

// ---------------- scratch (device globals; no allocation) ----------------
__device__ float d_ws[CIN * KW * CO];       // [(ci*27+k)*64 + o] folded sign*alpha*g
__device__ float d_shift[CO];
__device__ float d_y [NB * CO * TOUT];      // post BN+ELU
__device__ float d_qg[NB * CO * TOUT];      // (B,C,T)
__device__ float d_kg[NB * CO * TOUT];      // (B,C,T)
__device__ float d_vt[NB * TOUT * CO];      // (B,T,C)
__device__ float d_wqt[CO * CO];            // [c][o]
__device__ float d_wkt[CO * CO];
__device__ float d_wvt[CO * CO];
__device__ float d_wot[CO * CO];

// ---------------- prep: binarize+fold weights ----------------
__global__ void prep_weights(const float* __restrict__ w,
                             const float* __restrict__ cb,
                             const float* __restrict__ gamma,
                             const float* __restrict__ beta,
                             const float* __restrict__ mean,
                             const float* __restrict__ var) {
    int o = blockIdx.x;
    __shared__ float red[256];
    const float* wrow = w + o * (CIN * KW);
    float s = 0.f;
    for (int j = threadIdx.x; j < CIN * KW; j += 256) s += fabsf(wrow[j]);
    red[threadIdx.x] = s;
    __syncthreads();
    for (int st = 128; st > 0; st >>= 1) {
        if (threadIdx.x < st) red[threadIdx.x] += red[threadIdx.x + st];
        __syncthreads();
    }
    float alpha = red[0] * (1.f / (CIN * KW));
    float g = gamma[o] * rsqrtf(var[o] + 1e-5f);
    if (threadIdx.x == 0) d_shift[o] = (cb[o] - mean[o]) * g + beta[o];
    float ag = alpha * g;
    for (int j = threadIdx.x; j < CIN * KW; j += 256) {
        float wv = wrow[j];
        d_ws[j * CO + o] = (wv > 0.f) ? ag : ((wv < 0.f) ? -ag : 0.f);
    }
}

__global__ void prep_transpose(const float* __restrict__ wq, const float* __restrict__ wk,
                               const float* __restrict__ wv, const float* __restrict__ wo) {
    for (int j = threadIdx.x; j < CO * CO; j += 256) {
        int o = j >> 6, c = j & 63;
        d_wqt[c * CO + o] = wq[j];
        d_wkt[c * CO + o] = wk[j];
        d_wvt[c * CO + o] = wv[j];
        d_wot[c * CO + o] = wo[j];
    }
}

// ---------------- conv1d (binarized) + BN + ELU ----------------
// grid (10, 128): 64 t per block, all 64 co. thread: 4 co x 4 t.
__global__ __launch_bounds__(256) void conv_bn_elu(const float* __restrict__ x) {
    int t0  = blockIdx.x * 64;
    int b   = blockIdx.y;
    int tid = threadIdx.x;
    int cq  = tid & 15;          // co quad: co = cq*4 .. +3
    int tq  = tid >> 4;          // t quad:  t  = t0 + tq*4 .. +3
    __shared__ float sx[4][280];           // 4 ci x 279-wide input window
    __shared__ float sw[4 * KW * CO];      // 4 ci x 27 k x 64 co

    float acc[4][4];
    #pragma unroll
    for (int i = 0; i < 4; i++)
        #pragma unroll
        for (int j = 0; j < 4; j++) acc[i][j] = 0.f;

    int w0 = 4 * t0 - 13;
    const float* xb = x + (size_t)b * CIN * TIN;

    for (int cbase = 0; cbase < CIN; cbase += 4) {
        __syncthreads();
        for (int j = tid; j < 4 * 279; j += 256) {
            int cl = j / 279, p = j - cl * 279;
            int gp = w0 + p;
            sx[cl][p] = (gp >= 0 && gp < TIN) ? xb[(cbase + cl) * TIN + gp] : 0.f;
        }
        const float* wsrc = d_ws + cbase * KW * CO;
        for (int j = tid; j < 4 * KW * CO; j += 256) sw[j] = wsrc[j];
        __syncthreads();

        for (int cl = 0; cl < 4; cl++) {
            float xr[39];
            #pragma unroll
            for (int m = 0; m < 39; m++) xr[m] = sx[cl][tq * 16 + m];
            #pragma unroll
            for (int k = 0; k < KW; k++) {
                const float4 wv = *(const float4*)&sw[(cl * KW + k) * CO + cq * 4];
                #pragma unroll
                for (int it = 0; it < 4; it++) {
                    float xv = xr[4 * it + k];
                    acc[it][0] = fmaf(xv, wv.x, acc[it][0]);
                    acc[it][1] = fmaf(xv, wv.y, acc[it][1]);
                    acc[it][2] = fmaf(xv, wv.z, acc[it][2]);
                    acc[it][3] = fmaf(xv, wv.w, acc[it][3]);
                }
            }
        }
    }

    int co0 = cq * 4;
    int tb  = t0 + tq * 4;
    #pragma unroll
    for (int j = 0; j < 4; j++) {
        float sh = d_shift[co0 + j];
        #pragma unroll
        for (int it = 0; it < 4; it++) {
            int t = tb + it;
            if (t < TOUT) {
                float v = acc[it][j] + sh;
                v = (v > 0.f) ? v : expm1f(v);
                d_y[((size_t)b * CO + co0 + j) * TOUT + t] = v;
            }
        }
    }
}

// ---------------- q,k (spike-gated) and v projections ----------------
// grid (10, 128). thread: one o, 16 t's.
__global__ __launch_bounds__(256) void qkv_kernel() {
    int t0  = blockIdx.x * 64;
    int b   = blockIdx.y;
    int tid = threadIdx.x;
    int o   = tid & 63;
    int g   = tid >> 6;
    __shared__ float ys[CO][68];
    __shared__ float st[CO * 65];

    for (int j = tid; j < CO * 64; j += 256) {
        int c = j >> 6, tl = j & 63;
        int t = t0 + tl;
        ys[c][tl] = (t < TOUT) ? d_y[((size_t)b * CO + c) * TOUT + t] : 0.f;
    }
    __syncthreads();

    float qa[16], ka[16], va[16];
    #pragma unroll
    for (int i = 0; i < 16; i++) { qa[i] = 0.f; ka[i] = 0.f; va[i] = 0.f; }

    for (int c = 0; c < CO; c++) {
        float wqv = d_wqt[c * CO + o];
        float wkv = d_wkt[c * CO + o];
        float wvv = d_wvt[c * CO + o];
        #pragma unroll
        for (int jj = 0; jj < 4; jj++) {
            float4 yv = *(const float4*)&ys[c][g * 16 + jj * 4];
            float yy[4] = {yv.x, yv.y, yv.z, yv.w};
            #pragma unroll
            for (int e = 0; e < 4; e++) {
                int i = jj * 4 + e;
                float y1 = yy[e];
                if (y1 > 0.f) { qa[i] += wqv; ka[i] += wkv; }
                va[i] = fmaf(wvv, y1, va[i]);
            }
        }
    }

    // stage + coalesced store: q
    __syncthreads();
    #pragma unroll
    for (int i = 0; i < 16; i++) st[o * 65 + g * 16 + i] = qa[i];
    __syncthreads();
    for (int j = tid; j < CO * 64; j += 256) {
        int oo = j >> 6, tl = j & 63;
        int t = t0 + tl;
        if (t < TOUT) d_qg[((size_t)b * CO + oo) * TOUT + t] = st[oo * 65 + tl];
    }
    // k
    __syncthreads();
    #pragma unroll
    for (int i = 0; i < 16; i++) st[o * 65 + g * 16 + i] = ka[i];
    __syncthreads();
    for (int j = tid; j < CO * 64; j += 256) {
        int oo = j >> 6, tl = j & 63;
        int t = t0 + tl;
        if (t < TOUT) d_kg[((size_t)b * CO + oo) * TOUT + t] = st[oo * 65 + tl];
    }
    // v -> transposed (B,T,C)
    __syncthreads();
    #pragma unroll
    for (int i = 0; i < 16; i++) st[(g * 16 + i) * 65 + o] = va[i];
    __syncthreads();
    for (int j = tid; j < CO * 64; j += 256) {
        int tl = j >> 6, oo = j & 63;
        int t = t0 + tl;
        if (t < TOUT) d_vt[((size_t)b * TOUT + t) * CO + oo] = st[tl * 65 + oo];
    }
}

// ---------------- flash attention + wo + residual ----------------
// grid (10, 128). 64-query tile per block; thread: one query q, one 16-channel part.
__global__ __launch_bounds__(256) void attn_kernel(float* __restrict__ out) {
    extern __shared__ float sm[];
    float* qs   = sm;              // 4096: [c*64 + q]
    float* ks   = sm + 4096;       // 4096: [c*64 + s]   (reused for wot in epilogue)
    float* vs   = sm + 8192;       // 4096: [s*64 + c]
    float* ps   = sm + 12288;      // 64*65: [q*65 + s]  (reused for ctx)
    float* redm = sm + 16448;      // 256
    float* redl = sm + 16704;      // 256  -> total 16960 floats

    int t0   = blockIdx.x * 64;
    int b    = blockIdx.y;
    int tid  = threadIdx.x;
    int q    = tid & 63;
    int part = tid >> 6;
    int cb   = part * 16;

    for (int j = tid; j < 4096; j += 256) {
        int c = j >> 6, tl = j & 63;
        int t = t0 + tl;
        qs[j] = (t < TOUT) ? d_qg[((size_t)b * CO + c) * TOUT + t] : 0.f;
    }

    float m = -1e30f, l = 0.f;
    float a[16];
    #pragma unroll
    for (int i = 0; i < 16; i++) a[i] = 0.f;

    for (int stile = 0; stile < 10; stile++) {
        int s0 = stile * 64;
        __syncthreads();
        for (int j = tid; j < 4096; j += 256) {
            int c = j >> 6, sl = j & 63;
            int s = s0 + sl;
            ks[j] = (s < TOUT) ? d_kg[((size_t)b * CO + c) * TOUT + s] : 0.f;
        }
        for (int j = tid; j < 4096; j += 256) {
            int sl = j >> 6, c = j & 63;
            int s = s0 + sl;
            vs[j] = (s < TOUT) ? d_vt[((size_t)b * TOUT + s) * CO + c] : 0.f;
        }
        __syncthreads();

        float sc[16];
        #pragma unroll
        for (int i = 0; i < 16; i++) sc[i] = 0.f;
        for (int c = 0; c < CO; c++) {
            float qv = qs[c * 64 + q];
            const float4* kr = (const float4*)&ks[c * 64 + cb];
            float4 k0 = kr[0], k1 = kr[1], k2 = kr[2], k3 = kr[3];
            sc[0]  = fmaf(qv, k0.x, sc[0]);  sc[1]  = fmaf(qv, k0.y, sc[1]);
            sc[2]  = fmaf(qv, k0.z, sc[2]);  sc[3]  = fmaf(qv, k0.w, sc[3]);
            sc[4]  = fmaf(qv, k1.x, sc[4]);  sc[5]  = fmaf(qv, k1.y, sc[5]);
            sc[6]  = fmaf(qv, k1.z, sc[6]);  sc[7]  = fmaf(qv, k1.w, sc[7]);
            sc[8]  = fmaf(qv, k2.x, sc[8]);  sc[9]  = fmaf(qv, k2.y, sc[9]);
            sc[10] = fmaf(qv, k2.z, sc[10]); sc[11] = fmaf(qv, k2.w, sc[11]);
            sc[12] = fmaf(qv, k3.x, sc[12]); sc[13] = fmaf(qv, k3.y, sc[13]);
            sc[14] = fmaf(qv, k3.z, sc[14]); sc[15] = fmaf(qv, k3.w, sc[15]);
        }
        #pragma unroll
        for (int j2 = 0; j2 < 16; j2++) {
            sc[j2] *= 0.125f;                       // 1/sqrt(64)
            if (s0 + cb + j2 >= TOUT) sc[j2] = -1e30f;
        }
        float mp = sc[0];
        #pragma unroll
        for (int j2 = 1; j2 < 16; j2++) mp = fmaxf(mp, sc[j2]);
        redm[part * 64 + q] = mp;
        __syncthreads();
        float mnew = fmaxf(fmaxf(redm[q], redm[64 + q]), fmaxf(redm[128 + q], redm[192 + q]));
        mnew = fmaxf(m, mnew);
        float lp = 0.f;
        #pragma unroll
        for (int j2 = 0; j2 < 16; j2++) {
            float p = __expf(sc[j2] - mnew);
            ps[q * 65 + cb + j2] = p;
            lp += p;
        }
        redl[part * 64 + q] = lp;
        float corr = __expf(m - mnew);
        __syncthreads();
        float lt = redl[q] + redl[64 + q] + redl[128 + q] + redl[192 + q];
        l = l * corr + lt;
        m = mnew;
        #pragma unroll
        for (int i = 0; i < 16; i++) a[i] *= corr;
        for (int s = 0; s < 64; s++) {
            float pv = ps[q * 65 + s];
            const float4* vr = (const float4*)&vs[s * 64 + cb];
            float4 v0 = vr[0], v1 = vr[1], v2 = vr[2], v3 = vr[3];
            a[0]  = fmaf(pv, v0.x, a[0]);  a[1]  = fmaf(pv, v0.y, a[1]);
            a[2]  = fmaf(pv, v0.z, a[2]);  a[3]  = fmaf(pv, v0.w, a[3]);
            a[4]  = fmaf(pv, v1.x, a[4]);  a[5]  = fmaf(pv, v1.y, a[5]);
            a[6]  = fmaf(pv, v1.z, a[6]);  a[7]  = fmaf(pv, v1.w, a[7]);
            a[8]  = fmaf(pv, v2.x, a[8]);  a[9]  = fmaf(pv, v2.y, a[9]);
            a[10] = fmaf(pv, v2.z, a[10]); a[11] = fmaf(pv, v2.w, a[11]);
            a[12] = fmaf(pv, v3.x, a[12]); a[13] = fmaf(pv, v3.y, a[13]);
            a[14] = fmaf(pv, v3.z, a[14]); a[15] = fmaf(pv, v3.w, a[15]);
        }
    }

    __syncthreads();   // everyone done reading ps/ks from the mainloop
    float invl = 1.f / l;
    #pragma unroll
    for (int i = 0; i < 16; i++) ps[q * 65 + cb + i] = a[i] * invl;   // ctx
    for (int j = tid; j < 4096; j += 256) ks[j] = d_wot[j];           // wot[c][o]
    __syncthreads();

    float ob[16];
    #pragma unroll
    for (int i = 0; i < 16; i++) ob[i] = 0.f;
    for (int c = 0; c < CO; c++) {
        float cv = ps[q * 65 + c];
        const float4* wr = (const float4*)&ks[c * 64 + cb];
        float4 w0 = wr[0], w1 = wr[1], w2 = wr[2], w3 = wr[3];
        ob[0]  = fmaf(cv, w0.x, ob[0]);  ob[1]  = fmaf(cv, w0.y, ob[1]);
        ob[2]  = fmaf(cv, w0.z, ob[2]);  ob[3]  = fmaf(cv, w0.w, ob[3]);
        ob[4]  = fmaf(cv, w1.x, ob[4]);  ob[5]  = fmaf(cv, w1.y, ob[5]);
        ob[6]  = fmaf(cv, w1.z, ob[6]);  ob[7]  = fmaf(cv, w1.w, ob[7]);
        ob[8]  = fmaf(cv, w2.x, ob[8]);  ob[9]  = fmaf(cv, w2.y, ob[9]);
        ob[10] = fmaf(cv, w2.z, ob[10]); ob[11] = fmaf(cv, w2.w, ob[11]);
        ob[12] = fmaf(cv, w3.x, ob[12]); ob[13] = fmaf(cv, w3.y, ob[13]);
        ob[14] = fmaf(cv, w3.z, ob[14]); ob[15] = fmaf(cv, w3.w, ob[15]);
    }

    int t = t0 + q;
    if (t < TOUT) {
        #pragma unroll
        for (int i = 0; i < 16; i++) {
            int o = cb + i;
            out[((size_t)b * CO + o) * TOUT + t] =
                d_y[((size_t)b * CO + o) * TOUT + t] + ob[i];
        }
    }
}

// ---------------- launch ----------------
extern "C" void kernel_launch(void* const* d_in, const int* in_sizes, int n_in,
                              void* d_out, int out_size) {
    const float* x      = (const float*)d_in[0];
    const float* conv_w = (const float*)d_in[1];
    const float* conv_b = (const float*)d_in[2];
    const float* gamma  = (const float*)d_in[3];
    const float* beta   = (const float*)d_in[4];
    const float* mean   = (const float*)d_in[5];
    const float* var    = (const float*)d_in[6];
    const float* wq     = (const float*)d_in[7];
    const float* wk     = (const float*)d_in[8];
    const float* wv     = (const float*)d_in[9];
    const float* wo     = (const float*)d_in[10];
    float* out = (float*)d_out;

    prep_weights<<<64, 256>>>(conv_w, conv_b, gamma, beta, mean, var);
    prep_transpose<<<1, 256>>>(wq, wk, wv, wo);
    conv_bn_elu<<<dim3(10, NB), 256>>>(x);
    qkv_kernel<<<dim3(10, NB), 256>>>();

    const size_t att_smem = 16960 * sizeof(float);
    cudaFuncSetAttribute(attn_kernel, cudaFuncAttributeMaxDynamicSharedMemorySize,
                         (int)att_smem);
    attn_kernel<<<dim3(10, NB), 256, att_smem>>>(out);
}

// round 7
// speedup vs baseline: 1.2220x; 1.2220x over previous
#include <cuda_runtime.h>
#include <cuda_fp16.h>
#include <mma.h>
#include <math.h>
#include <stdint.h>

using namespace nvcuda;

#define NB   128
#define CIN  128
#define TIN  2500
#define CO   64
#define KW   27
#define TOUT 625
#define KTOT (CIN * KW)      // 3456
#define NKB  (KTOT / 32)     // 108 chunks of 32 original K (=64 hi/lo rows)

// ---------------- scratch (device globals; no allocation) ----------------
__device__ __half d_wh[NKB * 64 * 64];    // per-chunk sign rows, K' duplicated (hi/lo)
__device__ int4   d_tab4[KTOT / 2];       // {xoff0, koff0, xoff1, koff1}
__device__ float  d_scale[CO];            // alpha * gamma * rsqrt(var+eps)
__device__ float  d_shift[CO];
__device__ float  d_y [NB * CO * TOUT];   // post BN+ELU
__device__ float  d_qg[NB * CO * TOUT];   // (B,C,T)
__device__ float  d_kg[NB * CO * TOUT];   // (B,C,T)
__device__ float  d_vt[NB * TOUT * CO];   // (B,T,C)
__device__ float  d_wqt[CO * CO];         // [c][o]
__device__ float  d_wkt[CO * CO];
__device__ float  d_wvt[CO * CO];
__device__ float  d_wot[CO * CO];

// ---------------- prep: binarize weights -> fp16 sign tiles, scales, im2col table ----------------
__global__ void prep_weights(const float* __restrict__ w,
                             const float* __restrict__ cb,
                             const float* __restrict__ gamma,
                             const float* __restrict__ beta,
                             const float* __restrict__ mean,
                             const float* __restrict__ var) {
    int o = blockIdx.x;
    __shared__ float red[256];
    const float* wrow = w + o * KTOT;
    float s = 0.f;
    for (int j = threadIdx.x; j < KTOT; j += 256) s += fabsf(wrow[j]);
    red[threadIdx.x] = s;
    __syncthreads();
    for (int st = 128; st > 0; st >>= 1) {
        if (threadIdx.x < st) red[threadIdx.x] += red[threadIdx.x + st];
        __syncthreads();
    }
    float alpha = red[0] * (1.f / KTOT);
    float g = gamma[o] * rsqrtf(var[o] + 1e-5f);
    if (threadIdx.x == 0) {
        d_scale[o] = alpha * g;
        d_shift[o] = (cb[o] - mean[o]) * g + beta[o];
    }
    for (int K = threadIdx.x; K < KTOT; K += 256) {
        float wv = wrow[K];
        float sg = (wv > 0.f) ? 1.f : ((wv < 0.f) ? -1.f : 0.f);
        int kb = K >> 5, kl = K & 31;
        __half h = __float2half(sg);
        d_wh[kb * 4096 + (2 * kl)     * 64 + o] = h;   // hi row
        d_wh[kb * 4096 + (2 * kl + 1) * 64 + o] = h;   // lo row (same sign)
    }
}

__global__ void prep_transpose(const float* __restrict__ wq, const float* __restrict__ wk,
                               const float* __restrict__ wv, const float* __restrict__ wo) {
    for (int j = threadIdx.x; j < CO * CO; j += 256) {
        int o = j >> 6, c = j & 63;
        d_wqt[c * CO + o] = wq[j];
        d_wkt[c * CO + o] = wk[j];
        d_wvt[c * CO + o] = wv[j];
        d_wot[c * CO + o] = wo[j];
    }
    for (int j = threadIdx.x; j < KTOT / 2; j += 256) {
        int K0 = 2 * j, K1 = 2 * j + 1;
        int ci0 = K0 / 27, k0 = K0 - ci0 * 27;
        int ci1 = K1 / 27, k1 = K1 - ci1 * 27;
        d_tab4[j] = make_int4(ci0 * TIN * 4, k0 - 13,
                              ci1 * TIN * 4, k1 - 13);
    }
}

// ---------------- wmma fp16 (hi/lo split) implicit-GEMM conv + BN + ELU ----------------
// grid (5, 128): M=128 t, N=64 co, K'=6912 in 108 chunks of 64 fp16 rows.
// smem: A[2][128][72] half, B[2][64][72] half, epilogue C[128][72] float (aliased).
#define ALD   72
#define A_BYTES (128 * ALD * 2)     // 18432
#define B_BYTES (64 * ALD * 2)      // 9216
#define SM_CONV (2 * A_BYTES + 2 * B_BYTES)   // 55296

__global__ __launch_bounds__(256) void conv_wmma(const float* __restrict__ x) {
    extern __shared__ char smem[];
    __half* As[2] = { (__half*)smem, (__half*)(smem + A_BYTES) };
    __half* Bs[2] = { (__half*)(smem + 2 * A_BYTES), (__half*)(smem + 2 * A_BYTES + B_BYTES) };
    float*  Cs    = (float*)smem;

    int tid = threadIdx.x, wid = tid >> 5, lid = tid & 31;
    int t0 = blockIdx.x * 128;
    int b  = blockIdx.y;
    int warp_m = wid & 3;          // 4 warps along M (32 rows each)
    int warp_n = wid >> 2;         // 2 warps along N (32 cols each)

    const char* xb = (const char*)(x + (size_t)b * CIN * TIN);

    wmma::fragment<wmma::accumulator, 16, 16, 16, float> acc[2][2];
    #pragma unroll
    for (int i = 0; i < 2; i++)
        #pragma unroll
        for (int j = 0; j < 2; j++) wmma::fill_fragment(acc[i][j], 0.f);

    // ---- gather helpers (warp wid owns original-K lanes wid*4..wid*4+3) ----
    // prefetch chunk kb values into regs
    float vr[16];
    int4 bload[2];

    auto prefetch = [&](int kb) {
        int4 q0 = d_tab4[kb * 16 + wid * 2];
        int4 q1 = d_tab4[kb * 16 + wid * 2 + 1];
        int xoff[4] = {q0.x, q0.z, q1.x, q1.z};
        int koff[4] = {q0.y, q0.w, q1.y, q1.w};
        #pragma unroll
        for (int p = 0; p < 4; p++) {
            int tt = t0 + lid + p * 32;
            int p4 = tt * 4;
            #pragma unroll
            for (int e = 0; e < 4; e++) {
                int pos = p4 + koff[e];
                float vv = 0.f;
                if ((unsigned)pos < (unsigned)TIN)
                    vv = __ldg((const float*)(xb + xoff[e]) + pos);
                vr[p * 4 + e] = vv;
            }
        }
        // B tile prefetch: 2 int4 per thread (8KB total / 256 threads)
        const int4* bsrc = (const int4*)(d_wh + kb * 4096);
        bload[0] = __ldg(bsrc + tid);
        bload[1] = __ldg(bsrc + tid + 256);
    };

    auto stage = [&](int buf) {
        __half* A = As[buf];
        #pragma unroll
        for (int p = 0; p < 4; p++) {
            int t = lid + p * 32;
            #pragma unroll
            for (int e = 0; e < 4; e++) {
                float v  = vr[p * 4 + e];
                __half hi = __float2half_rn(v);
                __half lo = __float2half_rn(v - __half2float(hi));
                *(__half2*)&A[t * ALD + 2 * (wid * 4 + e)] = __halves2half2(hi, lo);
            }
        }
        // B: row = j>>3 (0..63), seg = j&7 (8 halves per int4)
        __half* B = Bs[buf];
        {
            int r0 = tid >> 3, s0 = tid & 7;
            *(int4*)&B[r0 * ALD + s0 * 8] = bload[0];
            int j1 = tid + 256;
            int r1 = j1 >> 3, s1 = j1 & 7;
            *(int4*)&B[r1 * ALD + s1 * 8] = bload[1];
        }
    };

    // ---- pipeline ----
    prefetch(0);
    stage(0);
    __syncthreads();

    for (int kb = 0; kb < NKB; kb++) {
        int buf = kb & 1;
        if (kb + 1 < NKB) prefetch(kb + 1);    // LDGs in flight under the MMAs

        const __half* A = As[buf];
        const __half* B = Bs[buf];
        #pragma unroll
        for (int kk = 0; kk < 4; kk++) {
            wmma::fragment<wmma::matrix_a, 16, 16, 16, __half, wmma::row_major> af[2];
            wmma::fragment<wmma::matrix_b, 16, 16, 16, __half, wmma::row_major> bf[2];
            #pragma unroll
            for (int i = 0; i < 2; i++)
                wmma::load_matrix_sync(af[i], A + (warp_m * 32 + i * 16) * ALD + kk * 16, ALD);
            #pragma unroll
            for (int j = 0; j < 2; j++)
                wmma::load_matrix_sync(bf[j], B + (kk * 16) * ALD + warp_n * 32 + j * 16, ALD);
            #pragma unroll
            for (int i = 0; i < 2; i++)
                #pragma unroll
                for (int j = 0; j < 2; j++)
                    wmma::mma_sync(acc[i][j], af[i], bf[j], acc[i][j]);
        }

        if (kb + 1 < NKB) stage(kb + 1 & 1 ? buf ^ 1 : buf ^ 1);  // always other buffer
        __syncthreads();
    }

    // ---- epilogue: store accums to smem C [128][72] f32, then BN+ELU -> d_y ----
    #pragma unroll
    for (int i = 0; i < 2; i++)
        #pragma unroll
        for (int j = 0; j < 2; j++)
            wmma::store_matrix_sync(Cs + (warp_m * 32 + i * 16) * ALD + warp_n * 32 + j * 16,
                                    acc[i][j], ALD, wmma::mem_row_major);
    __syncthreads();

    #pragma unroll
    for (int it = 0; it < 32; it++) {
        int idx = it * 256 + tid;
        int o  = idx >> 7;          // 0..63
        int tl = idx & 127;         // 0..127
        int t  = t0 + tl;
        if (t < TOUT) {
            float v = Cs[tl * ALD + o] * __ldg(d_scale + o) + __ldg(d_shift + o);
            v = (v > 0.f) ? v : expm1f(v);
            d_y[((size_t)b * CO + o) * TOUT + t] = v;
        }
    }
}

// ---------------- q,k (spike-gated) and v projections ----------------
__global__ __launch_bounds__(256) void qkv_kernel() {
    int t0  = blockIdx.x * 64;
    int b   = blockIdx.y;
    int tid = threadIdx.x;
    int o   = tid & 63;
    int g   = tid >> 6;
    __shared__ float ys[CO][68];
    __shared__ float st[CO * 65];

    for (int j = tid; j < CO * 64; j += 256) {
        int c = j >> 6, tl = j & 63;
        int t = t0 + tl;
        ys[c][tl] = (t < TOUT) ? d_y[((size_t)b * CO + c) * TOUT + t] : 0.f;
    }
    __syncthreads();

    float qa[16], ka[16], va[16];
    #pragma unroll
    for (int i = 0; i < 16; i++) { qa[i] = 0.f; ka[i] = 0.f; va[i] = 0.f; }

    for (int c = 0; c < CO; c++) {
        float wqv = d_wqt[c * CO + o];
        float wkv = d_wkt[c * CO + o];
        float wvv = d_wvt[c * CO + o];
        #pragma unroll
        for (int jj = 0; jj < 4; jj++) {
            float4 yv = *(const float4*)&ys[c][g * 16 + jj * 4];
            float yy[4] = {yv.x, yv.y, yv.z, yv.w};
            #pragma unroll
            for (int e = 0; e < 4; e++) {
                int i = jj * 4 + e;
                float y1 = yy[e];
                if (y1 > 0.f) { qa[i] += wqv; ka[i] += wkv; }
                va[i] = fmaf(wvv, y1, va[i]);
            }
        }
    }

    __syncthreads();
    #pragma unroll
    for (int i = 0; i < 16; i++) st[o * 65 + g * 16 + i] = qa[i];
    __syncthreads();
    for (int j = tid; j < CO * 64; j += 256) {
        int oo = j >> 6, tl = j & 63;
        int t = t0 + tl;
        if (t < TOUT) d_qg[((size_t)b * CO + oo) * TOUT + t] = st[oo * 65 + tl];
    }
    __syncthreads();
    #pragma unroll
    for (int i = 0; i < 16; i++) st[o * 65 + g * 16 + i] = ka[i];
    __syncthreads();
    for (int j = tid; j < CO * 64; j += 256) {
        int oo = j >> 6, tl = j & 63;
        int t = t0 + tl;
        if (t < TOUT) d_kg[((size_t)b * CO + oo) * TOUT + t] = st[oo * 65 + tl];
    }
    __syncthreads();
    #pragma unroll
    for (int i = 0; i < 16; i++) st[(g * 16 + i) * 65 + o] = va[i];
    __syncthreads();
    for (int j = tid; j < CO * 64; j += 256) {
        int tl = j >> 6, oo = j & 63;
        int t = t0 + tl;
        if (t < TOUT) d_vt[((size_t)b * TOUT + t) * CO + oo] = st[tl * 65 + oo];
    }
}

// ---------------- flash attention + wo + residual ----------------
__global__ __launch_bounds__(256) void attn_kernel(float* __restrict__ out) {
    extern __shared__ float sm[];
    float* qs   = sm;
    float* ks   = sm + 4096;
    float* vs   = sm + 8192;
    float* ps   = sm + 12288;
    float* redm = sm + 16448;
    float* redl = sm + 16704;

    int t0   = blockIdx.x * 64;
    int b    = blockIdx.y;
    int tid  = threadIdx.x;
    int q    = tid & 63;
    int part = tid >> 6;
    int cb   = part * 16;

    for (int j = tid; j < 4096; j += 256) {
        int c = j >> 6, tl = j & 63;
        int t = t0 + tl;
        qs[j] = (t < TOUT) ? d_qg[((size_t)b * CO + c) * TOUT + t] : 0.f;
    }

    float m = -1e30f, l = 0.f;
    float a[16];
    #pragma unroll
    for (int i = 0; i < 16; i++) a[i] = 0.f;

    for (int stile = 0; stile < 10; stile++) {
        int s0 = stile * 64;
        __syncthreads();
        for (int j = tid; j < 4096; j += 256) {
            int c = j >> 6, sl = j & 63;
            int s = s0 + sl;
            ks[j] = (s < TOUT) ? d_kg[((size_t)b * CO + c) * TOUT + s] : 0.f;
        }
        for (int j = tid; j < 4096; j += 256) {
            int sl = j >> 6, c = j & 63;
            int s = s0 + sl;
            vs[j] = (s < TOUT) ? d_vt[((size_t)b * TOUT + s) * CO + c] : 0.f;
        }
        __syncthreads();

        float sc[16];
        #pragma unroll
        for (int i = 0; i < 16; i++) sc[i] = 0.f;
        for (int c = 0; c < CO; c++) {
            float qv = qs[c * 64 + q];
            const float4* kr = (const float4*)&ks[c * 64 + cb];
            float4 k0 = kr[0], k1 = kr[1], k2 = kr[2], k3 = kr[3];
            sc[0]  = fmaf(qv, k0.x, sc[0]);  sc[1]  = fmaf(qv, k0.y, sc[1]);
            sc[2]  = fmaf(qv, k0.z, sc[2]);  sc[3]  = fmaf(qv, k0.w, sc[3]);
            sc[4]  = fmaf(qv, k1.x, sc[4]);  sc[5]  = fmaf(qv, k1.y, sc[5]);
            sc[6]  = fmaf(qv, k1.z, sc[6]);  sc[7]  = fmaf(qv, k1.w, sc[7]);
            sc[8]  = fmaf(qv, k2.x, sc[8]);  sc[9]  = fmaf(qv, k2.y, sc[9]);
            sc[10] = fmaf(qv, k2.z, sc[10]); sc[11] = fmaf(qv, k2.w, sc[11]);
            sc[12] = fmaf(qv, k3.x, sc[12]); sc[13] = fmaf(qv, k3.y, sc[13]);
            sc[14] = fmaf(qv, k3.z, sc[14]); sc[15] = fmaf(qv, k3.w, sc[15]);
        }
        #pragma unroll
        for (int j2 = 0; j2 < 16; j2++) {
            sc[j2] *= 0.125f;
            if (s0 + cb + j2 >= TOUT) sc[j2] = -1e30f;
        }
        float mp = sc[0];
        #pragma unroll
        for (int j2 = 1; j2 < 16; j2++) mp = fmaxf(mp, sc[j2]);
        redm[part * 64 + q] = mp;
        __syncthreads();
        float mnew = fmaxf(fmaxf(redm[q], redm[64 + q]), fmaxf(redm[128 + q], redm[192 + q]));
        mnew = fmaxf(m, mnew);
        float lp = 0.f;
        #pragma unroll
        for (int j2 = 0; j2 < 16; j2++) {
            float p = __expf(sc[j2] - mnew);
            ps[q * 65 + cb + j2] = p;
            lp += p;
        }
        redl[part * 64 + q] = lp;
        float corr = __expf(m - mnew);
        __syncthreads();
        float lt = redl[q] + redl[64 + q] + redl[128 + q] + redl[192 + q];
        l = l * corr + lt;
        m = mnew;
        #pragma unroll
        for (int i = 0; i < 16; i++) a[i] *= corr;
        for (int s = 0; s < 64; s++) {
            float pv = ps[q * 65 + s];
            const float4* vr = (const float4*)&vs[s * 64 + cb];
            float4 v0 = vr[0], v1 = vr[1], v2 = vr[2], v3 = vr[3];
            a[0]  = fmaf(pv, v0.x, a[0]);  a[1]  = fmaf(pv, v0.y, a[1]);
            a[2]  = fmaf(pv, v0.z, a[2]);  a[3]  = fmaf(pv, v0.w, a[3]);
            a[4]  = fmaf(pv, v1.x, a[4]);  a[5]  = fmaf(pv, v1.y, a[5]);
            a[6]  = fmaf(pv, v1.z, a[6]);  a[7]  = fmaf(pv, v1.w, a[7]);
            a[8]  = fmaf(pv, v2.x, a[8]);  a[9]  = fmaf(pv, v2.y, a[9]);
            a[10] = fmaf(pv, v2.z, a[10]); a[11] = fmaf(pv, v2.w, a[11]);
            a[12] = fmaf(pv, v3.x, a[12]); a[13] = fmaf(pv, v3.y, a[13]);
            a[14] = fmaf(pv, v3.z, a[14]); a[15] = fmaf(pv, v3.w, a[15]);
        }
    }

    __syncthreads();
    float invl = 1.f / l;
    #pragma unroll
    for (int i = 0; i < 16; i++) ps[q * 65 + cb + i] = a[i] * invl;
    for (int j = tid; j < 4096; j += 256) ks[j] = d_wot[j];
    __syncthreads();

    float ob[16];
    #pragma unroll
    for (int i = 0; i < 16; i++) ob[i] = 0.f;
    for (int c = 0; c < CO; c++) {
        float cv = ps[q * 65 + c];
        const float4* wr = (const float4*)&ks[c * 64 + cb];
        float4 w0 = wr[0], w1 = wr[1], w2 = wr[2], w3 = wr[3];
        ob[0]  = fmaf(cv, w0.x, ob[0]);  ob[1]  = fmaf(cv, w0.y, ob[1]);
        ob[2]  = fmaf(cv, w0.z, ob[2]);  ob[3]  = fmaf(cv, w0.w, ob[3]);
        ob[4]  = fmaf(cv, w1.x, ob[4]);  ob[5]  = fmaf(cv, w1.y, ob[5]);
        ob[6]  = fmaf(cv, w1.z, ob[6]);  ob[7]  = fmaf(cv, w1.w, ob[7]);
        ob[8]  = fmaf(cv, w2.x, ob[8]);  ob[9]  = fmaf(cv, w2.y, ob[9]);
        ob[10] = fmaf(cv, w2.z, ob[10]); ob[11] = fmaf(cv, w2.w, ob[11]);
        ob[12] = fmaf(cv, w3.x, ob[12]); ob[13] = fmaf(cv, w3.y, ob[13]);
        ob[14] = fmaf(cv, w3.z, ob[14]); ob[15] = fmaf(cv, w3.w, ob[15]);
    }

    int t = t0 + q;
    if (t < TOUT) {
        #pragma unroll
        for (int i = 0; i < 16; i++) {
            int o = cb + i;
            out[((size_t)b * CO + o) * TOUT + t] =
                d_y[((size_t)b * CO + o) * TOUT + t] + ob[i];
        }
    }
}

// ---------------- launch ----------------
extern "C" void kernel_launch(void* const* d_in, const int* in_sizes, int n_in,
                              void* d_out, int out_size) {
    const float* x      = (const float*)d_in[0];
    const float* conv_w = (const float*)d_in[1];
    const float* conv_b = (const float*)d_in[2];
    const float* gamma  = (const float*)d_in[3];
    const float* beta   = (const float*)d_in[4];
    const float* mean   = (const float*)d_in[5];
    const float* var    = (const float*)d_in[6];
    const float* wq     = (const float*)d_in[7];
    const float* wk     = (const float*)d_in[8];
    const float* wv     = (const float*)d_in[9];
    const float* wo     = (const float*)d_in[10];
    float* out = (float*)d_out;

    prep_weights<<<64, 256>>>(conv_w, conv_b, gamma, beta, mean, var);
    prep_transpose<<<1, 256>>>(wq, wk, wv, wo);

    cudaFuncSetAttribute(conv_wmma, cudaFuncAttributeMaxDynamicSharedMemorySize, SM_CONV);
    conv_wmma<<<dim3(5, NB), 256, SM_CONV>>>(x);

    qkv_kernel<<<dim3(10, NB), 256>>>();

    const size_t att_smem = 16960 * sizeof(float);
    cudaFuncSetAttribute(attn_kernel, cudaFuncAttributeMaxDynamicSharedMemorySize,
                         (int)att_smem);
    attn_kernel<<<dim3(10, NB), 256, att_smem>>>(out);
}

// round 8
// speedup vs baseline: 1.6435x; 1.3449x over previous
#include <cuda_runtime.h>
#include <cuda_fp16.h>
#include <mma.h>
#include <math.h>
#include <stdint.h>

using namespace nvcuda;

#define NB   128
#define CIN  128
#define TIN  2500
#define CO   64
#define KW   27
#define TOUT 625
#define KTOT (CIN * KW)      // 3456
#define NKB  (KTOT / 32)     // 108 chunks of 32 original K (=64 hi/lo rows)

// ---------------- scratch (device globals; no allocation) ----------------
__device__ __half d_wh[NKB * 64 * 64];    // per-chunk sign rows, K' duplicated (hi/lo)
__device__ int4   d_tab4[KTOT / 2];       // {xoff0, koff0, xoff1, koff1}
__device__ float  d_scale[CO];
__device__ float  d_shift[CO];
__device__ float  d_y [NB * CO * TOUT];   // post BN+ELU (fp32, for residual + v)
__device__ __half d_qh[NB * TOUT * CO];   // (B,T,C) half
__device__ __half d_kh[NB * CO * TOUT];   // (B,C,T) half
__device__ __half d_vh[NB * TOUT * CO];   // (B,T,C) half
__device__ float  d_wqt[CO * CO];         // [c][o]
__device__ float  d_wkt[CO * CO];
__device__ float  d_wvt[CO * CO];
__device__ float  d_wot[CO * CO];

// ---------------- prep ----------------
__global__ void prep_weights(const float* __restrict__ w,
                             const float* __restrict__ cb,
                             const float* __restrict__ gamma,
                             const float* __restrict__ beta,
                             const float* __restrict__ mean,
                             const float* __restrict__ var) {
    int o = blockIdx.x;
    __shared__ float red[256];
    const float* wrow = w + o * KTOT;
    float s = 0.f;
    for (int j = threadIdx.x; j < KTOT; j += 256) s += fabsf(wrow[j]);
    red[threadIdx.x] = s;
    __syncthreads();
    for (int st = 128; st > 0; st >>= 1) {
        if (threadIdx.x < st) red[threadIdx.x] += red[threadIdx.x + st];
        __syncthreads();
    }
    float alpha = red[0] * (1.f / KTOT);
    float g = gamma[o] * rsqrtf(var[o] + 1e-5f);
    if (threadIdx.x == 0) {
        d_scale[o] = alpha * g;
        d_shift[o] = (cb[o] - mean[o]) * g + beta[o];
    }
    for (int K = threadIdx.x; K < KTOT; K += 256) {
        float wv = wrow[K];
        float sg = (wv > 0.f) ? 1.f : ((wv < 0.f) ? -1.f : 0.f);
        int kb = K >> 5, kl = K & 31;
        __half h = __float2half(sg);
        d_wh[kb * 4096 + (2 * kl)     * 64 + o] = h;
        d_wh[kb * 4096 + (2 * kl + 1) * 64 + o] = h;
    }
}

__global__ void prep_transpose(const float* __restrict__ wq, const float* __restrict__ wk,
                               const float* __restrict__ wv, const float* __restrict__ wo) {
    for (int j = threadIdx.x; j < CO * CO; j += 256) {
        int o = j >> 6, c = j & 63;
        d_wqt[c * CO + o] = wq[j];
        d_wkt[c * CO + o] = wk[j];
        d_wvt[c * CO + o] = wv[j];
        d_wot[c * CO + o] = wo[j];
    }
    for (int j = threadIdx.x; j < KTOT / 2; j += 256) {
        int K0 = 2 * j, K1 = 2 * j + 1;
        int ci0 = K0 / 27, k0 = K0 - ci0 * 27;
        int ci1 = K1 / 27, k1 = K1 - ci1 * 27;
        d_tab4[j] = make_int4(ci0 * TIN * 4, k0 - 13,
                              ci1 * TIN * 4, k1 - 13);
    }
}

// ---------------- wmma fp16 (hi/lo split) implicit-GEMM conv + BN + ELU ----------------
#define ALD   72
#define A_BYTES (128 * ALD * 2)
#define B_BYTES (64 * ALD * 2)
#define SM_CONV (2 * A_BYTES + 2 * B_BYTES)   // 55296

__global__ __launch_bounds__(256) void conv_wmma(const float* __restrict__ x) {
    extern __shared__ char smem[];
    __half* As[2] = { (__half*)smem, (__half*)(smem + A_BYTES) };
    __half* Bs[2] = { (__half*)(smem + 2 * A_BYTES), (__half*)(smem + 2 * A_BYTES + B_BYTES) };
    float*  Cs    = (float*)smem;

    int tid = threadIdx.x, wid = tid >> 5, lid = tid & 31;
    int t0 = blockIdx.x * 128;
    int b  = blockIdx.y;
    int warp_m = wid & 3;
    int warp_n = wid >> 2;

    const char* xb = (const char*)(x + (size_t)b * CIN * TIN);

    wmma::fragment<wmma::accumulator, 16, 16, 16, float> acc[2][2];
    #pragma unroll
    for (int i = 0; i < 2; i++)
        #pragma unroll
        for (int j = 0; j < 2; j++) wmma::fill_fragment(acc[i][j], 0.f);

    float vr[16];
    int4 bload[2];

    auto prefetch = [&](int kb) {
        int4 q0 = d_tab4[kb * 16 + wid * 2];
        int4 q1 = d_tab4[kb * 16 + wid * 2 + 1];
        int xoff[4] = {q0.x, q0.z, q1.x, q1.z};
        int koff[4] = {q0.y, q0.w, q1.y, q1.w};
        #pragma unroll
        for (int p = 0; p < 4; p++) {
            int tt = t0 + lid + p * 32;
            int p4 = tt * 4;
            #pragma unroll
            for (int e = 0; e < 4; e++) {
                int pos = p4 + koff[e];
                float vv = 0.f;
                if ((unsigned)pos < (unsigned)TIN)
                    vv = __ldg((const float*)(xb + xoff[e]) + pos);
                vr[p * 4 + e] = vv;
            }
        }
        const int4* bsrc = (const int4*)(d_wh + kb * 4096);
        bload[0] = __ldg(bsrc + tid);
        bload[1] = __ldg(bsrc + tid + 256);
    };

    auto stage = [&](int buf) {
        __half* A = As[buf];
        #pragma unroll
        for (int p = 0; p < 4; p++) {
            int t = lid + p * 32;
            #pragma unroll
            for (int e = 0; e < 4; e++) {
                float v  = vr[p * 4 + e];
                __half hi = __float2half_rn(v);
                __half lo = __float2half_rn(v - __half2float(hi));
                *(__half2*)&A[t * ALD + 2 * (wid * 4 + e)] = __halves2half2(hi, lo);
            }
        }
        __half* B = Bs[buf];
        {
            int r0 = tid >> 3, s0 = tid & 7;
            *(int4*)&B[r0 * ALD + s0 * 8] = bload[0];
            int j1 = tid + 256;
            int r1 = j1 >> 3, s1 = j1 & 7;
            *(int4*)&B[r1 * ALD + s1 * 8] = bload[1];
        }
    };

    prefetch(0);
    stage(0);
    __syncthreads();

    for (int kb = 0; kb < NKB; kb++) {
        int buf = kb & 1;
        if (kb + 1 < NKB) prefetch(kb + 1);

        const __half* A = As[buf];
        const __half* B = Bs[buf];
        #pragma unroll
        for (int kk = 0; kk < 4; kk++) {
            wmma::fragment<wmma::matrix_a, 16, 16, 16, __half, wmma::row_major> af[2];
            wmma::fragment<wmma::matrix_b, 16, 16, 16, __half, wmma::row_major> bf[2];
            #pragma unroll
            for (int i = 0; i < 2; i++)
                wmma::load_matrix_sync(af[i], A + (warp_m * 32 + i * 16) * ALD + kk * 16, ALD);
            #pragma unroll
            for (int j = 0; j < 2; j++)
                wmma::load_matrix_sync(bf[j], B + (kk * 16) * ALD + warp_n * 32 + j * 16, ALD);
            #pragma unroll
            for (int i = 0; i < 2; i++)
                #pragma unroll
                for (int j = 0; j < 2; j++)
                    wmma::mma_sync(acc[i][j], af[i], bf[j], acc[i][j]);
        }

        if (kb + 1 < NKB) stage(buf ^ 1);
        __syncthreads();
    }

    #pragma unroll
    for (int i = 0; i < 2; i++)
        #pragma unroll
        for (int j = 0; j < 2; j++)
            wmma::store_matrix_sync(Cs + (warp_m * 32 + i * 16) * ALD + warp_n * 32 + j * 16,
                                    acc[i][j], ALD, wmma::mem_row_major);
    __syncthreads();

    #pragma unroll
    for (int it = 0; it < 32; it++) {
        int idx = it * 256 + tid;
        int o  = idx >> 7;
        int tl = idx & 127;
        int t  = t0 + tl;
        if (t < TOUT) {
            float v = Cs[tl * ALD + o] * __ldg(d_scale + o) + __ldg(d_shift + o);
            v = (v > 0.f) ? v : expm1f(v);
            d_y[((size_t)b * CO + o) * TOUT + t] = v;
        }
    }
}

// ---------------- q,k (spike-gated) and v projections -> fp16 ----------------
__global__ __launch_bounds__(256) void qkv_kernel() {
    int t0  = blockIdx.x * 64;
    int b   = blockIdx.y;
    int tid = threadIdx.x;
    int o   = tid & 63;
    int g   = tid >> 6;
    __shared__ float ys[CO][68];
    __shared__ float st[CO * 65];

    for (int j = tid; j < CO * 64; j += 256) {
        int c = j >> 6, tl = j & 63;
        int t = t0 + tl;
        ys[c][tl] = (t < TOUT) ? d_y[((size_t)b * CO + c) * TOUT + t] : 0.f;
    }
    __syncthreads();

    float qa[16], ka[16], va[16];
    #pragma unroll
    for (int i = 0; i < 16; i++) { qa[i] = 0.f; ka[i] = 0.f; va[i] = 0.f; }

    for (int c = 0; c < CO; c++) {
        float wqv = d_wqt[c * CO + o];
        float wkv = d_wkt[c * CO + o];
        float wvv = d_wvt[c * CO + o];
        #pragma unroll
        for (int jj = 0; jj < 4; jj++) {
            float4 yv = *(const float4*)&ys[c][g * 16 + jj * 4];
            float yy[4] = {yv.x, yv.y, yv.z, yv.w};
            #pragma unroll
            for (int e = 0; e < 4; e++) {
                int i = jj * 4 + e;
                float y1 = yy[e];
                if (y1 > 0.f) { qa[i] += wqv; ka[i] += wkv; }
                va[i] = fmaf(wvv, y1, va[i]);
            }
        }
    }

    // q -> (B,T,C) half
    __syncthreads();
    #pragma unroll
    for (int i = 0; i < 16; i++) st[(g * 16 + i) * 65 + o] = qa[i];
    __syncthreads();
    for (int j = tid; j < CO * 64; j += 256) {
        int tl = j >> 6, oo = j & 63;
        int t = t0 + tl;
        if (t < TOUT) d_qh[((size_t)b * TOUT + t) * CO + oo] = __float2half(st[tl * 65 + oo]);
    }
    // k -> (B,C,T) half
    __syncthreads();
    #pragma unroll
    for (int i = 0; i < 16; i++) st[o * 65 + g * 16 + i] = ka[i];
    __syncthreads();
    for (int j = tid; j < CO * 64; j += 256) {
        int oo = j >> 6, tl = j & 63;
        int t = t0 + tl;
        if (t < TOUT) d_kh[((size_t)b * CO + oo) * TOUT + t] = __float2half(st[oo * 65 + tl]);
    }
    // v -> (B,T,C) half
    __syncthreads();
    #pragma unroll
    for (int i = 0; i < 16; i++) st[(g * 16 + i) * 65 + o] = va[i];
    __syncthreads();
    for (int j = tid; j < CO * 64; j += 256) {
        int tl = j >> 6, oo = j & 63;
        int t = t0 + tl;
        if (t < TOUT) d_vh[((size_t)b * TOUT + t) * CO + oo] = __float2half(st[tl * 65 + oo]);
    }
}

// ---------------- wmma attention (fixed-shift softmax) + wo + residual ----------------
// smem layout (bytes):
#define QH_OFF   0          // 64*72 half  = 9216
#define KH_OFF   9216       // 64*72 half  = 9216
#define VH_OFF   18432      // 64*72 half  = 9216
#define PH_OFF   27648      // 64*72 half  = 9216
#define SF_OFF   36864      // 64*68 f32   = 17408  (aliased as ctx at end)
#define RL_OFF   54272      // 256 f32     = 1024
#define SM_ATT   55296
// wot (fp32 4096 floats = 16KB) aliases QH/KH region in the epilogue.

__global__ __launch_bounds__(256) void attn_wmma(float* __restrict__ out) {
    extern __shared__ char smem[];
    __half* Qh = (__half*)(smem + QH_OFF);
    __half* Kh = (__half*)(smem + KH_OFF);
    __half* Vh = (__half*)(smem + VH_OFF);
    __half* Ph = (__half*)(smem + PH_OFF);
    float*  Sf = (float*)(smem + SF_OFF);
    float*  redl = (float*)(smem + RL_OFF);
    float*  wot_s = (float*)(smem + QH_OFF);   // epilogue alias

    int t0   = blockIdx.x * 64;
    int b    = blockIdx.y;
    int tid  = threadIdx.x;
    int wid  = tid >> 5;
    int q    = tid & 63;
    int part = tid >> 6;
    int cb   = part * 16;
    int warp_m = wid & 3;      // 16 q-rows
    int warp_n = wid >> 2;     // 32 s-cols (2 frags)

    // load Q tile (T,C) -> Qh[q][c]
    for (int j = tid; j < 4096; j += 256) {
        int tl = j >> 6, c = j & 63;
        int t = t0 + tl;
        Qh[tl * 72 + c] = (t < TOUT) ? d_qh[((size_t)b * TOUT + t) * CO + c]
                                     : __float2half(0.f);
    }

    wmma::fragment<wmma::accumulator, 16, 16, 16, float> ctx[2];
    #pragma unroll
    for (int j = 0; j < 2; j++) wmma::fill_fragment(ctx[j], 0.f);

    float l = 0.f;

    for (int stile = 0; stile < 10; stile++) {
        int s0 = stile * 64;
        __syncthreads();   // (a) previous PV done; Kh/Vh/Ph reusable (also covers Qh load)

        for (int j = tid; j < 4096; j += 256) {
            int c = j >> 6, sl = j & 63;
            int s = s0 + sl;
            Kh[c * 72 + sl] = (s < TOUT) ? d_kh[((size_t)b * CO + c) * TOUT + s]
                                         : __float2half(0.f);
        }
        for (int j = tid; j < 4096; j += 256) {
            int sl = j >> 6, c = j & 63;
            int s = s0 + sl;
            Vh[sl * 72 + c] = (s < TOUT) ? d_vh[((size_t)b * TOUT + s) * CO + c]
                                         : __float2half(0.f);
        }
        __syncthreads();   // (b) tiles ready

        // S = Q K  (64x64x64)
        {
            wmma::fragment<wmma::accumulator, 16, 16, 16, float> sacc[2];
            #pragma unroll
            for (int j = 0; j < 2; j++) wmma::fill_fragment(sacc[j], 0.f);
            #pragma unroll
            for (int kk = 0; kk < 4; kk++) {
                wmma::fragment<wmma::matrix_a, 16, 16, 16, __half, wmma::row_major> af;
                wmma::fragment<wmma::matrix_b, 16, 16, 16, __half, wmma::row_major> bf[2];
                wmma::load_matrix_sync(af, Qh + (warp_m * 16) * 72 + kk * 16, 72);
                #pragma unroll
                for (int j = 0; j < 2; j++)
                    wmma::load_matrix_sync(bf[j], Kh + (kk * 16) * 72 + warp_n * 32 + j * 16, 72);
                #pragma unroll
                for (int j = 0; j < 2; j++)
                    wmma::mma_sync(sacc[j], af, bf[j], sacc[j]);
            }
            #pragma unroll
            for (int j = 0; j < 2; j++)
                wmma::store_matrix_sync(Sf + (warp_m * 16) * 68 + warp_n * 32 + j * 16,
                                        sacc[j], 68, wmma::mem_row_major);
        }
        __syncthreads();   // (c) scores visible

        // softmax chunk (fixed shift 0): p = exp(s/8), masked
        {
            float lp = 0.f;
            const float4* sr = (const float4*)&Sf[q * 68 + cb];
            float4 s4[4] = { sr[0], sr[1], sr[2], sr[3] };
            float sv[16] = { s4[0].x, s4[0].y, s4[0].z, s4[0].w,
                             s4[1].x, s4[1].y, s4[1].z, s4[1].w,
                             s4[2].x, s4[2].y, s4[2].z, s4[2].w,
                             s4[3].x, s4[3].y, s4[3].z, s4[3].w };
            #pragma unroll
            for (int i = 0; i < 16; i++) {
                int sg = s0 + cb + i;
                float p = (sg < TOUT) ? __expf(sv[i] * 0.125f) : 0.f;
                Ph[q * 72 + cb + i] = __float2half(p);
                lp += p;
            }
            redl[part * 64 + q] = lp;
        }
        __syncthreads();   // (d) P + partial l visible

        l += redl[q] + redl[64 + q] + redl[128 + q] + redl[192 + q];

        // ctx += P V  (64x64x64), accumulator persists (no rescale needed)
        #pragma unroll
        for (int kk = 0; kk < 4; kk++) {
            wmma::fragment<wmma::matrix_a, 16, 16, 16, __half, wmma::row_major> af;
            wmma::fragment<wmma::matrix_b, 16, 16, 16, __half, wmma::row_major> bf[2];
            wmma::load_matrix_sync(af, Ph + (warp_m * 16) * 72 + kk * 16, 72);
            #pragma unroll
            for (int j = 0; j < 2; j++)
                wmma::load_matrix_sync(bf[j], Vh + (kk * 16) * 72 + warp_n * 32 + j * 16, 72);
            #pragma unroll
            for (int j = 0; j < 2; j++)
                wmma::mma_sync(ctx[j], af, bf[j], ctx[j]);
        }
    }

    __syncthreads();
    // store ctx to Sf (alias ok: scores no longer needed)
    #pragma unroll
    for (int j = 0; j < 2; j++)
        wmma::store_matrix_sync(Sf + (warp_m * 16) * 68 + warp_n * 32 + j * 16,
                                ctx[j], 68, wmma::mem_row_major);
    // wot into smem (aliases Qh/Kh region — safe after last S GEMM)
    for (int j = tid; j < 4096; j += 256) wot_s[j] = d_wot[j];
    __syncthreads();

    float invl = 1.f / l;
    float ob[16];
    #pragma unroll
    for (int i = 0; i < 16; i++) ob[i] = 0.f;
    for (int c = 0; c < CO; c++) {
        float cv = Sf[q * 68 + c] * invl;
        const float4* wr = (const float4*)&wot_s[c * 64 + cb];
        float4 w0 = wr[0], w1 = wr[1], w2 = wr[2], w3 = wr[3];
        ob[0]  = fmaf(cv, w0.x, ob[0]);  ob[1]  = fmaf(cv, w0.y, ob[1]);
        ob[2]  = fmaf(cv, w0.z, ob[2]);  ob[3]  = fmaf(cv, w0.w, ob[3]);
        ob[4]  = fmaf(cv, w1.x, ob[4]);  ob[5]  = fmaf(cv, w1.y, ob[5]);
        ob[6]  = fmaf(cv, w1.z, ob[6]);  ob[7]  = fmaf(cv, w1.w, ob[7]);
        ob[8]  = fmaf(cv, w2.x, ob[8]);  ob[9]  = fmaf(cv, w2.y, ob[9]);
        ob[10] = fmaf(cv, w2.z, ob[10]); ob[11] = fmaf(cv, w2.w, ob[11]);
        ob[12] = fmaf(cv, w3.x, ob[12]); ob[13] = fmaf(cv, w3.y, ob[13]);
        ob[14] = fmaf(cv, w3.z, ob[14]); ob[15] = fmaf(cv, w3.w, ob[15]);
    }

    int t = t0 + q;
    if (t < TOUT) {
        #pragma unroll
        for (int i = 0; i < 16; i++) {
            int o = cb + i;
            out[((size_t)b * CO + o) * TOUT + t] =
                d_y[((size_t)b * CO + o) * TOUT + t] + ob[i];
        }
    }
}

// ---------------- launch ----------------
extern "C" void kernel_launch(void* const* d_in, const int* in_sizes, int n_in,
                              void* d_out, int out_size) {
    const float* x      = (const float*)d_in[0];
    const float* conv_w = (const float*)d_in[1];
    const float* conv_b = (const float*)d_in[2];
    const float* gamma  = (const float*)d_in[3];
    const float* beta   = (const float*)d_in[4];
    const float* mean   = (const float*)d_in[5];
    const float* var    = (const float*)d_in[6];
    const float* wq     = (const float*)d_in[7];
    const float* wk     = (const float*)d_in[8];
    const float* wv     = (const float*)d_in[9];
    const float* wo     = (const float*)d_in[10];
    float* out = (float*)d_out;

    prep_weights<<<64, 256>>>(conv_w, conv_b, gamma, beta, mean, var);
    prep_transpose<<<1, 256>>>(wq, wk, wv, wo);

    cudaFuncSetAttribute(conv_wmma, cudaFuncAttributeMaxDynamicSharedMemorySize, SM_CONV);
    conv_wmma<<<dim3(5, NB), 256, SM_CONV>>>(x);

    qkv_kernel<<<dim3(10, NB), 256>>>();

    cudaFuncSetAttribute(attn_wmma, cudaFuncAttributeMaxDynamicSharedMemorySize, SM_ATT);
    attn_wmma<<<dim3(10, NB), 256, SM_ATT>>>(out);
}

// round 9
// speedup vs baseline: 1.6851x; 1.0253x over previous
#include <cuda_runtime.h>
#include <cuda_fp16.h>
#include <mma.h>
#include <math.h>
#include <stdint.h>

using namespace nvcuda;

#define NB   128
#define CIN  128
#define TIN  2500
#define CO   64
#define KW   27
#define TOUT 625
#define KTOT (CIN * KW)      // 3456
#define NKB2 54              // chunks of 64 original K (=128 hi/lo rows)

// ---------------- scratch (device globals; no allocation) ----------------
__device__ __half d_wh[108 * 64 * 64];    // per-32-chunk pre-ordered sign rows (hi/lo dup)
__device__ int4   d_tab4[KTOT / 2];       // {xoff0, koff0, xoff1, koff1}
__device__ float  d_scale[CO];
__device__ float  d_shift[CO];
__device__ float  d_y [NB * CO * TOUT];   // post BN+ELU (fp32, residual + spike source)
__device__ __half d_qh[NB * TOUT * CO];   // (B,T,C) half
__device__ __half d_kh[NB * CO * TOUT];   // (B,C,T) half
__device__ __half d_vh[NB * TOUT * CO];   // (B,T,C) half
__device__ __half d_wqkvh[192 * 128];     // stacked [wq|0; wk|0; 0|wv] fp16
__device__ float  d_wot[CO * CO];         // [c][o]

// ---------------- prep ----------------
__global__ void prep_weights(const float* __restrict__ w,
                             const float* __restrict__ cb,
                             const float* __restrict__ gamma,
                             const float* __restrict__ beta,
                             const float* __restrict__ mean,
                             const float* __restrict__ var) {
    int o = blockIdx.x;
    __shared__ float red[256];
    const float* wrow = w + o * KTOT;
    float s = 0.f;
    for (int j = threadIdx.x; j < KTOT; j += 256) s += fabsf(wrow[j]);
    red[threadIdx.x] = s;
    __syncthreads();
    for (int st = 128; st > 0; st >>= 1) {
        if (threadIdx.x < st) red[threadIdx.x] += red[threadIdx.x + st];
        __syncthreads();
    }
    float alpha = red[0] * (1.f / KTOT);
    float g = gamma[o] * rsqrtf(var[o] + 1e-5f);
    if (threadIdx.x == 0) {
        d_scale[o] = alpha * g;
        d_shift[o] = (cb[o] - mean[o]) * g + beta[o];
    }
    for (int K = threadIdx.x; K < KTOT; K += 256) {
        float wv = wrow[K];
        float sg = (wv > 0.f) ? 1.f : ((wv < 0.f) ? -1.f : 0.f);
        int kb = K >> 5, kl = K & 31;
        __half h = __float2half(sg);
        d_wh[kb * 4096 + (2 * kl)     * 64 + o] = h;
        d_wh[kb * 4096 + (2 * kl + 1) * 64 + o] = h;
    }
}

__global__ void prep_misc(const float* __restrict__ wq, const float* __restrict__ wk,
                          const float* __restrict__ wv, const float* __restrict__ wo) {
    for (int j = threadIdx.x; j < CO * CO; j += 256) {
        int o = j >> 6, c = j & 63;
        d_wot[c * CO + o] = wo[j];
    }
    for (int j = threadIdx.x; j < 192 * 128; j += 256) {
        int m = j >> 7, k = j & 127;
        float v = 0.f;
        if (m < 64)        { if (k < 64)  v = wq[m * 64 + k]; }
        else if (m < 128)  { if (k < 64)  v = wk[(m - 64) * 64 + k]; }
        else               { if (k >= 64) v = wv[(m - 128) * 64 + (k - 64)]; }
        d_wqkvh[j] = __float2half(v);
    }
    for (int j = threadIdx.x; j < KTOT / 2; j += 256) {
        int K0 = 2 * j, K1 = 2 * j + 1;
        int ci0 = K0 / 27, k0 = K0 - ci0 * 27;
        int ci1 = K1 / 27, k1 = K1 - ci1 * 27;
        d_tab4[j] = make_int4(ci0 * TIN * 4, k0 - 13,
                              ci1 * TIN * 4, k1 - 13);
    }
}

// ---------------- wmma fp16 (hi/lo split) implicit-GEMM conv + BN + ELU ----------------
// grid (5, 128): M=128 t, N=64 co, K'=6912 in 54 chunks of 128 fp16 rows.
#define ALD2 136
#define BLD  72
#define A2_BYTES (128 * ALD2 * 2)    // 34816
#define B2_BYTES (128 * BLD * 2)     // 18432
#define SM_CONV (2 * A2_BYTES + 2 * B2_BYTES)   // 106496

__global__ __launch_bounds__(256) void conv_wmma(const float* __restrict__ x) {
    extern __shared__ char smem[];
    __half* As[2] = { (__half*)smem, (__half*)(smem + A2_BYTES) };
    __half* Bs[2] = { (__half*)(smem + 2 * A2_BYTES), (__half*)(smem + 2 * A2_BYTES + B2_BYTES) };
    float*  Cs    = (float*)smem;    // epilogue alias: 128*72*4 = 36864

    int tid = threadIdx.x, wid = tid >> 5, lid = tid & 31;
    int t0 = blockIdx.x * 128;
    int b  = blockIdx.y;
    int warp_m = wid & 3;
    int warp_n = wid >> 2;

    const char* xb = (const char*)(x + (size_t)b * CIN * TIN);

    wmma::fragment<wmma::accumulator, 16, 16, 16, float> acc[2][2];
    #pragma unroll
    for (int i = 0; i < 2; i++)
        #pragma unroll
        for (int j = 0; j < 2; j++) wmma::fill_fragment(acc[i][j], 0.f);

    float vr[32];
    int4  bload[4];

    auto prefetch = [&](int ib) {
        int xoff[8], koff[8];
        #pragma unroll
        for (int e2 = 0; e2 < 4; e2++) {
            int4 qd = d_tab4[ib * 32 + wid * 4 + e2];
            xoff[2 * e2]     = qd.x; koff[2 * e2]     = qd.y;
            xoff[2 * e2 + 1] = qd.z; koff[2 * e2 + 1] = qd.w;
        }
        #pragma unroll
        for (int p = 0; p < 4; p++) {
            int tt = t0 + lid + p * 32;
            int p4 = tt * 4;
            #pragma unroll
            for (int e = 0; e < 8; e++) {
                int pos = p4 + koff[e];
                float vv = 0.f;
                if ((unsigned)pos < (unsigned)TIN)
                    vv = __ldg((const float*)(xb + xoff[e]) + pos);
                vr[p * 8 + e] = vv;
            }
        }
        const int4* bsrc = (const int4*)(d_wh + ib * 8192);
        #pragma unroll
        for (int e2 = 0; e2 < 4; e2++) bload[e2] = __ldg(bsrc + tid + e2 * 256);
    };

    auto stage = [&](int buf) {
        __half* A = As[buf];
        #pragma unroll
        for (int p = 0; p < 4; p++) {
            int t = lid + p * 32;
            #pragma unroll
            for (int e = 0; e < 8; e++) {
                float v  = vr[p * 8 + e];
                __half hi = __float2half_rn(v);
                __half lo = __float2half_rn(v - __half2float(hi));
                *(__half2*)&A[t * ALD2 + 2 * (wid * 8 + e)] = __halves2half2(hi, lo);
            }
        }
        __half* B = Bs[buf];
        #pragma unroll
        for (int e2 = 0; e2 < 4; e2++) {
            int idx = tid + e2 * 256;
            int r = idx >> 3, s = idx & 7;
            *(int4*)&B[r * BLD + s * 8] = bload[e2];
        }
    };

    prefetch(0);
    stage(0);
    __syncthreads();

    for (int ib = 0; ib < NKB2; ib++) {
        int buf = ib & 1;
        if (ib + 1 < NKB2) prefetch(ib + 1);   // 36 LDGs in flight under the MMAs

        const __half* A = As[buf];
        const __half* B = Bs[buf];
        #pragma unroll
        for (int kk = 0; kk < 8; kk++) {
            wmma::fragment<wmma::matrix_a, 16, 16, 16, __half, wmma::row_major> af[2];
            wmma::fragment<wmma::matrix_b, 16, 16, 16, __half, wmma::row_major> bf[2];
            #pragma unroll
            for (int i = 0; i < 2; i++)
                wmma::load_matrix_sync(af[i], A + (warp_m * 32 + i * 16) * ALD2 + kk * 16, ALD2);
            #pragma unroll
            for (int j = 0; j < 2; j++)
                wmma::load_matrix_sync(bf[j], B + (kk * 16) * BLD + warp_n * 32 + j * 16, BLD);
            #pragma unroll
            for (int i = 0; i < 2; i++)
                #pragma unroll
                for (int j = 0; j < 2; j++)
                    wmma::mma_sync(acc[i][j], af[i], bf[j], acc[i][j]);
        }

        if (ib + 1 < NKB2) stage(buf ^ 1);
        __syncthreads();
    }

    #pragma unroll
    for (int i = 0; i < 2; i++)
        #pragma unroll
        for (int j = 0; j < 2; j++)
            wmma::store_matrix_sync(Cs + (warp_m * 32 + i * 16) * 72 + warp_n * 32 + j * 16,
                                    acc[i][j], 72, wmma::mem_row_major);
    __syncthreads();

    #pragma unroll
    for (int it = 0; it < 32; it++) {
        int idx = it * 256 + tid;
        int o  = idx >> 7;
        int tl = idx & 127;
        int t  = t0 + tl;
        if (t < TOUT) {
            float v = Cs[tl * 72 + o] * __ldg(d_scale + o) + __ldg(d_shift + o);
            v = (v > 0.f) ? v : expm1f(v);
            d_y[((size_t)b * CO + o) * TOUT + t] = v;
        }
    }
}

// ---------------- qkv as one wmma GEMM: [192x128] x [128x64] ----------------
// B rows 0-63 = spike(y) (exact in fp16), rows 64-127 = y (fp16).
#define QB_OFF 0                      // Bh 128x72 half = 18432
#define QA_OFF 18432                  // Ah 192x136 half = 52224
#define QC_OFF 18432                  // Cs alias over Ah: 192x68 f32 = 52224
#define SM_QKV (18432 + 52224)        // 70656

__global__ __launch_bounds__(256) void qkv_gemm() {
    extern __shared__ char smem[];
    __half* Bh = (__half*)(smem + QB_OFF);
    __half* Ah = (__half*)(smem + QA_OFF);
    float*  Cs = (float*)(smem + QC_OFF);

    int t0  = blockIdx.x * 64;
    int b   = blockIdx.y;
    int tid = threadIdx.x;
    int wid = tid >> 5;
    int warp_m = wid & 3;      // 48 rows (3 frags)
    int warp_n = wid >> 2;     // 32 cols (2 frags)

    // B tile: spike + y
    for (int j = tid; j < 4096; j += 256) {
        int c = j >> 6, tl = j & 63;
        int t = t0 + tl;
        float yv = (t < TOUT) ? d_y[((size_t)b * CO + c) * TOUT + t] : 0.f;
        Bh[c * BLD + tl]        = __float2half(yv > 0.f ? 1.f : 0.f);
        Bh[(64 + c) * BLD + tl] = __float2half(yv);
    }
    // A tile: 3072 int4
    {
        const int4* asrc = (const int4*)d_wqkvh;
        #pragma unroll
        for (int e = 0; e < 12; e++) {
            int idx = tid + e * 256;
            int m = idx >> 4, seg = idx & 15;
            *(int4*)&Ah[m * 136 + seg * 8] = __ldg(asrc + idx);
        }
    }
    __syncthreads();

    wmma::fragment<wmma::accumulator, 16, 16, 16, float> acc[3][2];
    #pragma unroll
    for (int i = 0; i < 3; i++)
        #pragma unroll
        for (int j = 0; j < 2; j++) wmma::fill_fragment(acc[i][j], 0.f);

    #pragma unroll
    for (int kk = 0; kk < 8; kk++) {
        wmma::fragment<wmma::matrix_a, 16, 16, 16, __half, wmma::row_major> af[3];
        wmma::fragment<wmma::matrix_b, 16, 16, 16, __half, wmma::row_major> bf[2];
        #pragma unroll
        for (int i = 0; i < 3; i++)
            wmma::load_matrix_sync(af[i], Ah + (warp_m * 48 + i * 16) * 136 + kk * 16, 136);
        #pragma unroll
        for (int j = 0; j < 2; j++)
            wmma::load_matrix_sync(bf[j], Bh + (kk * 16) * BLD + warp_n * 32 + j * 16, BLD);
        #pragma unroll
        for (int i = 0; i < 3; i++)
            #pragma unroll
            for (int j = 0; j < 2; j++)
                wmma::mma_sync(acc[i][j], af[i], bf[j], acc[i][j]);
    }
    __syncthreads();   // all MMA reads of Ah done before Cs alias write

    #pragma unroll
    for (int i = 0; i < 3; i++)
        #pragma unroll
        for (int j = 0; j < 2; j++)
            wmma::store_matrix_sync(Cs + (warp_m * 48 + i * 16) * 68 + warp_n * 32 + j * 16,
                                    acc[i][j], 68, wmma::mem_row_major);
    __syncthreads();

    // q -> (B,T,C)
    for (int j = tid; j < 4096; j += 256) {
        int tl = j >> 6, o = j & 63;
        int t = t0 + tl;
        if (t < TOUT) d_qh[((size_t)b * TOUT + t) * CO + o] = __float2half(Cs[o * 68 + tl]);
    }
    // k -> (B,C,T)
    for (int j = tid; j < 4096; j += 256) {
        int o = j >> 6, tl = j & 63;
        int t = t0 + tl;
        if (t < TOUT) d_kh[((size_t)b * CO + o) * TOUT + t] = __float2half(Cs[(64 + o) * 68 + tl]);
    }
    // v -> (B,T,C)
    for (int j = tid; j < 4096; j += 256) {
        int tl = j >> 6, o = j & 63;
        int t = t0 + tl;
        if (t < TOUT) d_vh[((size_t)b * TOUT + t) * CO + o] = __float2half(Cs[(128 + o) * 68 + tl]);
    }
}

// ---------------- wmma attention (fixed-shift softmax) + wo + residual ----------------
#define QH_OFF   0
#define KH_OFF   9216
#define VH_OFF   18432
#define PH_OFF   27648
#define SF_OFF   36864
#define RL_OFF   54272
#define SM_ATT   55296

__global__ __launch_bounds__(256) void attn_wmma(float* __restrict__ out) {
    extern __shared__ char smem[];
    __half* Qh = (__half*)(smem + QH_OFF);
    __half* Kh = (__half*)(smem + KH_OFF);
    __half* Vh = (__half*)(smem + VH_OFF);
    __half* Ph = (__half*)(smem + PH_OFF);
    float*  Sf = (float*)(smem + SF_OFF);
    float*  redl = (float*)(smem + RL_OFF);
    float*  wot_s = (float*)(smem + QH_OFF);

    int t0   = blockIdx.x * 64;
    int b    = blockIdx.y;
    int tid  = threadIdx.x;
    int wid  = tid >> 5;
    int q    = tid & 63;
    int part = tid >> 6;
    int cb   = part * 16;
    int warp_m = wid & 3;
    int warp_n = wid >> 2;

    for (int j = tid; j < 4096; j += 256) {
        int tl = j >> 6, c = j & 63;
        int t = t0 + tl;
        Qh[tl * 72 + c] = (t < TOUT) ? d_qh[((size_t)b * TOUT + t) * CO + c]
                                     : __float2half(0.f);
    }

    wmma::fragment<wmma::accumulator, 16, 16, 16, float> ctx[2];
    #pragma unroll
    for (int j = 0; j < 2; j++) wmma::fill_fragment(ctx[j], 0.f);

    float l = 0.f;

    for (int stile = 0; stile < 10; stile++) {
        int s0 = stile * 64;
        __syncthreads();

        for (int j = tid; j < 4096; j += 256) {
            int c = j >> 6, sl = j & 63;
            int s = s0 + sl;
            Kh[c * 72 + sl] = (s < TOUT) ? d_kh[((size_t)b * CO + c) * TOUT + s]
                                         : __float2half(0.f);
        }
        for (int j = tid; j < 4096; j += 256) {
            int sl = j >> 6, c = j & 63;
            int s = s0 + sl;
            Vh[sl * 72 + c] = (s < TOUT) ? d_vh[((size_t)b * TOUT + s) * CO + c]
                                         : __float2half(0.f);
        }
        __syncthreads();

        {
            wmma::fragment<wmma::accumulator, 16, 16, 16, float> sacc[2];
            #pragma unroll
            for (int j = 0; j < 2; j++) wmma::fill_fragment(sacc[j], 0.f);
            #pragma unroll
            for (int kk = 0; kk < 4; kk++) {
                wmma::fragment<wmma::matrix_a, 16, 16, 16, __half, wmma::row_major> af;
                wmma::fragment<wmma::matrix_b, 16, 16, 16, __half, wmma::row_major> bf[2];
                wmma::load_matrix_sync(af, Qh + (warp_m * 16) * 72 + kk * 16, 72);
                #pragma unroll
                for (int j = 0; j < 2; j++)
                    wmma::load_matrix_sync(bf[j], Kh + (kk * 16) * 72 + warp_n * 32 + j * 16, 72);
                #pragma unroll
                for (int j = 0; j < 2; j++)
                    wmma::mma_sync(sacc[j], af, bf[j], sacc[j]);
            }
            #pragma unroll
            for (int j = 0; j < 2; j++)
                wmma::store_matrix_sync(Sf + (warp_m * 16) * 68 + warp_n * 32 + j * 16,
                                        sacc[j], 68, wmma::mem_row_major);
        }
        __syncthreads();

        {
            float lp = 0.f;
            const float4* sr = (const float4*)&Sf[q * 68 + cb];
            float4 s4[4] = { sr[0], sr[1], sr[2], sr[3] };
            float sv[16] = { s4[0].x, s4[0].y, s4[0].z, s4[0].w,
                             s4[1].x, s4[1].y, s4[1].z, s4[1].w,
                             s4[2].x, s4[2].y, s4[2].z, s4[2].w,
                             s4[3].x, s4[3].y, s4[3].z, s4[3].w };
            #pragma unroll
            for (int i = 0; i < 16; i++) {
                int sg = s0 + cb + i;
                float p = (sg < TOUT) ? __expf(sv[i] * 0.125f) : 0.f;
                Ph[q * 72 + cb + i] = __float2half(p);
                lp += p;
            }
            redl[part * 64 + q] = lp;
        }
        __syncthreads();

        l += redl[q] + redl[64 + q] + redl[128 + q] + redl[192 + q];

        #pragma unroll
        for (int kk = 0; kk < 4; kk++) {
            wmma::fragment<wmma::matrix_a, 16, 16, 16, __half, wmma::row_major> af;
            wmma::fragment<wmma::matrix_b, 16, 16, 16, __half, wmma::row_major> bf[2];
            wmma::load_matrix_sync(af, Ph + (warp_m * 16) * 72 + kk * 16, 72);
            #pragma unroll
            for (int j = 0; j < 2; j++)
                wmma::load_matrix_sync(bf[j], Vh + (kk * 16) * 72 + warp_n * 32 + j * 16, 72);
            #pragma unroll
            for (int j = 0; j < 2; j++)
                wmma::mma_sync(ctx[j], af, bf[j], ctx[j]);
        }
    }

    __syncthreads();
    #pragma unroll
    for (int j = 0; j < 2; j++)
        wmma::store_matrix_sync(Sf + (warp_m * 16) * 68 + warp_n * 32 + j * 16,
                                ctx[j], 68, wmma::mem_row_major);
    for (int j = tid; j < 4096; j += 256) wot_s[j] = d_wot[j];
    __syncthreads();

    float invl = 1.f / l;
    float ob[16];
    #pragma unroll
    for (int i = 0; i < 16; i++) ob[i] = 0.f;
    for (int c = 0; c < CO; c++) {
        float cv = Sf[q * 68 + c] * invl;
        const float4* wr = (const float4*)&wot_s[c * 64 + cb];
        float4 w0 = wr[0], w1 = wr[1], w2 = wr[2], w3 = wr[3];
        ob[0]  = fmaf(cv, w0.x, ob[0]);  ob[1]  = fmaf(cv, w0.y, ob[1]);
        ob[2]  = fmaf(cv, w0.z, ob[2]);  ob[3]  = fmaf(cv, w0.w, ob[3]);
        ob[4]  = fmaf(cv, w1.x, ob[4]);  ob[5]  = fmaf(cv, w1.y, ob[5]);
        ob[6]  = fmaf(cv, w1.z, ob[6]);  ob[7]  = fmaf(cv, w1.w, ob[7]);
        ob[8]  = fmaf(cv, w2.x, ob[8]);  ob[9]  = fmaf(cv, w2.y, ob[9]);
        ob[10] = fmaf(cv, w2.z, ob[10]); ob[11] = fmaf(cv, w2.w, ob[11]);
        ob[12] = fmaf(cv, w3.x, ob[12]); ob[13] = fmaf(cv, w3.y, ob[13]);
        ob[14] = fmaf(cv, w3.z, ob[14]); ob[15] = fmaf(cv, w3.w, ob[15]);
    }

    int t = t0 + q;
    if (t < TOUT) {
        #pragma unroll
        for (int i = 0; i < 16; i++) {
            int o = cb + i;
            out[((size_t)b * CO + o) * TOUT + t] =
                d_y[((size_t)b * CO + o) * TOUT + t] + ob[i];
        }
    }
}

// ---------------- launch ----------------
extern "C" void kernel_launch(void* const* d_in, const int* in_sizes, int n_in,
                              void* d_out, int out_size) {
    const float* x      = (const float*)d_in[0];
    const float* conv_w = (const float*)d_in[1];
    const float* conv_b = (const float*)d_in[2];
    const float* gamma  = (const float*)d_in[3];
    const float* beta   = (const float*)d_in[4];
    const float* mean   = (const float*)d_in[5];
    const float* var    = (const float*)d_in[6];
    const float* wq     = (const float*)d_in[7];
    const float* wk     = (const float*)d_in[8];
    const float* wv     = (const float*)d_in[9];
    const float* wo     = (const float*)d_in[10];
    float* out = (float*)d_out;

    prep_weights<<<64, 256>>>(conv_w, conv_b, gamma, beta, mean, var);
    prep_misc<<<1, 256>>>(wq, wk, wv, wo);

    cudaFuncSetAttribute(conv_wmma, cudaFuncAttributeMaxDynamicSharedMemorySize, SM_CONV);
    conv_wmma<<<dim3(5, NB), 256, SM_CONV>>>(x);

    cudaFuncSetAttribute(qkv_gemm, cudaFuncAttributeMaxDynamicSharedMemorySize, SM_QKV);
    qkv_gemm<<<dim3(10, NB), 256, SM_QKV>>>();

    cudaFuncSetAttribute(attn_wmma, cudaFuncAttributeMaxDynamicSharedMemorySize, SM_ATT);
    attn_wmma<<<dim3(10, NB), 256, SM_ATT>>>(out);
}

// round 11
// speedup vs baseline: 1.6898x; 1.0028x over previous
#include <cuda_runtime.h>
#include <cuda_fp16.h>
#include <mma.h>
#include <math.h>
#include <stdint.h>

using namespace nvcuda;

#define NB   128
#define CIN  128
#define TIN  2500
#define CO   64
#define KW   27
#define TOUT 625
#define KTOT (CIN * KW)      // 3456
#define NKB2 54              // chunks of 64 original K (=128 hi/lo rows)

// ---------------- scratch (device globals; no allocation) ----------------
__device__ __half d_wh[108 * 64 * 64];        // per-32-chunk sign rows (hi/lo dup)
__device__ unsigned long long d_ktab64[NKB2 * 8];  // per-K byte: (s<<6)|(r<<4)|a
__device__ float  d_scale[CO];
__device__ float  d_shift[CO];
__device__ float  d_y [NB * CO * TOUT];
__device__ __half d_qh[NB * TOUT * CO];       // (B,T,C)
__device__ __half d_kh[NB * CO * TOUT];       // (B,C,T)
__device__ __half d_vh[NB * TOUT * CO];       // (B,T,C)
__device__ __half d_wqkvh[192 * 128];
__device__ float  d_wot[CO * CO];

// ---------------- prep ----------------
__global__ void prep_weights(const float* __restrict__ w,
                             const float* __restrict__ cb,
                             const float* __restrict__ gamma,
                             const float* __restrict__ beta,
                             const float* __restrict__ mean,
                             const float* __restrict__ var) {
    int o = blockIdx.x;
    __shared__ float red[256];
    const float* wrow = w + o * KTOT;
    float s = 0.f;
    for (int j = threadIdx.x; j < KTOT; j += 256) s += fabsf(wrow[j]);
    red[threadIdx.x] = s;
    __syncthreads();
    for (int st = 128; st > 0; st >>= 1) {
        if (threadIdx.x < st) red[threadIdx.x] += red[threadIdx.x + st];
        __syncthreads();
    }
    float alpha = red[0] * (1.f / KTOT);
    float g = gamma[o] * rsqrtf(var[o] + 1e-5f);
    if (threadIdx.x == 0) {
        d_scale[o] = alpha * g;
        d_shift[o] = (cb[o] - mean[o]) * g + beta[o];
    }
    for (int K = threadIdx.x; K < KTOT; K += 256) {
        float wv = wrow[K];
        float sg = (wv > 0.f) ? 1.f : ((wv < 0.f) ? -1.f : 0.f);
        int kb = K >> 5, kl = K & 31;
        __half h = __float2half(sg);
        d_wh[kb * 4096 + (2 * kl)     * 64 + o] = h;
        d_wh[kb * 4096 + (2 * kl + 1) * 64 + o] = h;
    }
}

__global__ void prep_misc(const float* __restrict__ wq, const float* __restrict__ wk,
                          const float* __restrict__ wv, const float* __restrict__ wo) {
    for (int j = threadIdx.x; j < CO * CO; j += 256) {
        int o = j >> 6, c = j & 63;
        d_wot[c * CO + o] = wo[j];
    }
    for (int j = threadIdx.x; j < 192 * 128; j += 256) {
        int m = j >> 7, k = j & 127;
        float v = 0.f;
        if (m < 64)        { if (k < 64)  v = wq[m * 64 + k]; }
        else if (m < 128)  { if (k < 64)  v = wk[(m - 64) * 64 + k]; }
        else               { if (k >= 64) v = wv[(m - 128) * 64 + (k - 64)]; }
        d_wqkvh[j] = __float2half(v);
    }
    for (int K = threadIdx.x; K < KTOT; K += 256) {
        int ib = K >> 6, e = K & 63;
        int ci = K / 27, k = K - 27 * ci;
        int s  = ci - (64 * ib) / 27;        // 0..3
        ((uint8_t*)d_ktab64)[ib * 64 + e] =
            (uint8_t)((s << 6) | ((k & 3) << 4) | (k >> 2));
    }
}

// ---------------- wmma fp16 (hi/lo) implicit-GEMM conv + BN + ELU ----------------
// grid (5, 128): M=128 t, N=64 co, 54 chunks of 128 hi/lo rows.
// x windows: per chunk <=4 ci rows, each a contiguous 536-float window,
// stored transposed-by-residue for conflict-free A-build LDS.
#define ALD2 136
#define BLD  72
#define A2_BYTES (128 * ALD2 * 2)    // 34816
#define B2_BYTES (128 * BLD * 2)     // 18432
#define XW_OFF   (2 * A2_BYTES + 2 * B2_BYTES)  // 106496
#define XW_BYTES (4 * 4 * 136 * 4)   // 8704 per buffer
#define SM_CONV  (XW_OFF + 2 * XW_BYTES)        // 123904

__global__ __launch_bounds__(256) void conv_wmma(const float* __restrict__ x) {
    extern __shared__ char smem[];
    __half* As[2] = { (__half*)smem, (__half*)(smem + A2_BYTES) };
    __half* Bs[2] = { (__half*)(smem + 2 * A2_BYTES), (__half*)(smem + 2 * A2_BYTES + B2_BYTES) };
    float*  Xw[2] = { (float*)(smem + XW_OFF), (float*)(smem + XW_OFF + XW_BYTES) };
    float*  Cs    = (float*)smem;

    int tid = threadIdx.x, wid = tid >> 5, lid = tid & 31;
    int t0 = blockIdx.x * 128;
    int b  = blockIdx.y;
    int warp_m = wid & 3;
    int warp_n = wid >> 2;
    int w0 = 4 * t0 - 13;

    const float* xb = x + (size_t)b * CIN * TIN;

    wmma::fragment<wmma::accumulator, 16, 16, 16, float> acc[2][2];
    #pragma unroll
    for (int i = 0; i < 2; i++)
        #pragma unroll
        for (int j = 0; j < 2; j++) wmma::fill_fragment(acc[i][j], 0.f);

    float wreg[9];
    int4  bload[4];

    // load window+B data for chunk ibn into registers
    auto load_regs = [&](int ibn) {
        int ci0 = (64 * ibn) / 27;
        #pragma unroll
        for (int i = 0; i < 9; i++) {
            int j2 = tid + i * 256;
            float v = 0.f;
            if (j2 < 2176) {
                int slot = j2 / 544, j = j2 - slot * 544;
                int ci = ci0 + slot;
                int gp = w0 + j;
                if (j < 536 && ci < CIN && (unsigned)gp < (unsigned)TIN)
                    v = __ldg(xb + ci * TIN + gp);
            }
            wreg[i] = v;
        }
        const int4* bsrc = (const int4*)(d_wh + ibn * 8192);
        #pragma unroll
        for (int e2 = 0; e2 < 4; e2++) bload[e2] = __ldg(bsrc + tid + e2 * 256);
    };

    // store window regs into transposed smem layout
    auto sts_win = [&](int buf) {
        float* W = Xw[buf];
        #pragma unroll
        for (int i = 0; i < 9; i++) {
            int j2 = tid + i * 256;
            if (j2 < 2176) {
                int slot = j2 / 544, j = j2 - slot * 544;
                W[slot * 544 + (j & 3) * 136 + (j >> 2)] = wreg[i];
            }
        }
    };

    // build A (from Xw[buf]) and B (from bload) into smem buffers
    auto build = [&](int ibn, int buf) {
        unsigned long long pk8 = d_ktab64[ibn * 8 + wid];
        int off[8];
        #pragma unroll
        for (int e = 0; e < 8; e++) {
            int pk = (int)((pk8 >> (8 * e)) & 255ull);
            off[e] = (pk >> 6) * 544 + ((pk >> 4) & 3) * 136 + (pk & 15);
        }
        const float* W = Xw[buf];
        __half* A = As[buf];
        #pragma unroll
        for (int p = 0; p < 4; p++) {
            int t = lid + p * 32;
            #pragma unroll
            for (int eh = 0; eh < 2; eh++) {
                __half2 h2[4];
                #pragma unroll
                for (int q = 0; q < 4; q++) {
                    float v = W[off[eh * 4 + q] + t];
                    __half hi = __float2half_rn(v);
                    __half lo = __float2half_rn(v - __half2float(hi));
                    h2[q] = __halves2half2(hi, lo);
                }
                int4 pack;
                pack.x = *(int*)&h2[0]; pack.y = *(int*)&h2[1];
                pack.z = *(int*)&h2[2]; pack.w = *(int*)&h2[3];
                *(int4*)&A[t * ALD2 + wid * 16 + eh * 8] = pack;
            }
        }
        __half* B = Bs[buf];
        #pragma unroll
        for (int e2 = 0; e2 < 4; e2++) {
            int idx = tid + e2 * 256;
            int r = idx >> 3, sgt = idx & 7;
            *(int4*)&B[r * BLD + sgt * 8] = bload[e2];
        }
    };

    // ---- preamble: window 0 + build 0 ----
    load_regs(0);
    sts_win(0);
    __syncthreads();
    build(0, 0);
    __syncthreads();

    for (int ib = 0; ib < NKB2; ib++) {
        int buf = ib & 1;
        if (ib + 1 < NKB2) load_regs(ib + 1);   // LDGs in flight under MMAs

        const __half* A = As[buf];
        const __half* B = Bs[buf];
        #pragma unroll
        for (int kk = 0; kk < 8; kk++) {
            wmma::fragment<wmma::matrix_a, 16, 16, 16, __half, wmma::row_major> af[2];
            wmma::fragment<wmma::matrix_b, 16, 16, 16, __half, wmma::row_major> bf[2];
            #pragma unroll
            for (int i = 0; i < 2; i++)
                wmma::load_matrix_sync(af[i], A + (warp_m * 32 + i * 16) * ALD2 + kk * 16, ALD2);
            #pragma unroll
            for (int j = 0; j < 2; j++)
                wmma::load_matrix_sync(bf[j], B + (kk * 16) * BLD + warp_n * 32 + j * 16, BLD);
            #pragma unroll
            for (int i = 0; i < 2; i++)
                #pragma unroll
                for (int j = 0; j < 2; j++)
                    wmma::mma_sync(acc[i][j], af[i], bf[j], acc[i][j]);
        }

        if (ib + 1 < NKB2) {
            sts_win(buf ^ 1);
            __syncthreads();        // window STS visible before build LDS
            build(ib + 1, buf ^ 1);
            __syncthreads();        // A/B[buf^1] ready for next MMA
        }
    }
    __syncthreads();                // all MMAs done before Cs alias write

    #pragma unroll
    for (int i = 0; i < 2; i++)
        #pragma unroll
        for (int j = 0; j < 2; j++)
            wmma::store_matrix_sync(Cs + (warp_m * 32 + i * 16) * 72 + warp_n * 32 + j * 16,
                                    acc[i][j], 72, wmma::mem_row_major);
    __syncthreads();

    #pragma unroll
    for (int it = 0; it < 32; it++) {
        int idx = it * 256 + tid;
        int o  = idx >> 7;
        int tl = idx & 127;
        int t  = t0 + tl;
        if (t < TOUT) {
            float v = Cs[tl * 72 + o] * __ldg(d_scale + o) + __ldg(d_shift + o);
            v = (v > 0.f) ? v : expm1f(v);
            d_y[((size_t)b * CO + o) * TOUT + t] = v;
        }
    }
}

// ---------------- qkv as one wmma GEMM: [192x128] x [128x64] ----------------
#define QB_OFF 0
#define QA_OFF 18432
#define QC_OFF 18432
#define SM_QKV (18432 + 52224)

__global__ __launch_bounds__(256) void qkv_gemm() {
    extern __shared__ char smem[];
    __half* Bh = (__half*)(smem + QB_OFF);
    __half* Ah = (__half*)(smem + QA_OFF);
    float*  Cs = (float*)(smem + QC_OFF);

    int t0  = blockIdx.x * 64;
    int b   = blockIdx.y;
    int tid = threadIdx.x;
    int wid = tid >> 5;
    int warp_m = wid & 3;
    int warp_n = wid >> 2;

    for (int j = tid; j < 4096; j += 256) {
        int c = j >> 6, tl = j & 63;
        int t = t0 + tl;
        float yv = (t < TOUT) ? d_y[((size_t)b * CO + c) * TOUT + t] : 0.f;
        Bh[c * BLD + tl]        = __float2half(yv > 0.f ? 1.f : 0.f);
        Bh[(64 + c) * BLD + tl] = __float2half(yv);
    }
    {
        const int4* asrc = (const int4*)d_wqkvh;
        #pragma unroll
        for (int e = 0; e < 12; e++) {
            int idx = tid + e * 256;
            int m = idx >> 4, seg = idx & 15;
            *(int4*)&Ah[m * 136 + seg * 8] = __ldg(asrc + idx);
        }
    }
    __syncthreads();

    wmma::fragment<wmma::accumulator, 16, 16, 16, float> acc[3][2];
    #pragma unroll
    for (int i = 0; i < 3; i++)
        #pragma unroll
        for (int j = 0; j < 2; j++) wmma::fill_fragment(acc[i][j], 0.f);

    #pragma unroll
    for (int kk = 0; kk < 8; kk++) {
        wmma::fragment<wmma::matrix_a, 16, 16, 16, __half, wmma::row_major> af[3];
        wmma::fragment<wmma::matrix_b, 16, 16, 16, __half, wmma::row_major> bf[2];
        #pragma unroll
        for (int i = 0; i < 3; i++)
            wmma::load_matrix_sync(af[i], Ah + (warp_m * 48 + i * 16) * 136 + kk * 16, 136);
        #pragma unroll
        for (int j = 0; j < 2; j++)
            wmma::load_matrix_sync(bf[j], Bh + (kk * 16) * BLD + warp_n * 32 + j * 16, BLD);
        #pragma unroll
        for (int i = 0; i < 3; i++)
            #pragma unroll
            for (int j = 0; j < 2; j++)
                wmma::mma_sync(acc[i][j], af[i], bf[j], acc[i][j]);
    }
    __syncthreads();

    #pragma unroll
    for (int i = 0; i < 3; i++)
        #pragma unroll
        for (int j = 0; j < 2; j++)
            wmma::store_matrix_sync(Cs + (warp_m * 48 + i * 16) * 68 + warp_n * 32 + j * 16,
                                    acc[i][j], 68, wmma::mem_row_major);
    __syncthreads();

    for (int j = tid; j < 4096; j += 256) {
        int tl = j >> 6, o = j & 63;
        int t = t0 + tl;
        if (t < TOUT) d_qh[((size_t)b * TOUT + t) * CO + o] = __float2half(Cs[o * 68 + tl]);
    }
    for (int j = tid; j < 4096; j += 256) {
        int o = j >> 6, tl = j & 63;
        int t = t0 + tl;
        if (t < TOUT) d_kh[((size_t)b * CO + o) * TOUT + t] = __float2half(Cs[(64 + o) * 68 + tl]);
    }
    for (int j = tid; j < 4096; j += 256) {
        int tl = j >> 6, o = j & 63;
        int t = t0 + tl;
        if (t < TOUT) d_vh[((size_t)b * TOUT + t) * CO + o] = __float2half(Cs[(128 + o) * 68 + tl]);
    }
}

// ---------------- wmma attention (fixed-shift softmax) + wo + residual ----------------
#define QH_OFF   0
#define KH_OFF   9216
#define VH_OFF   18432
#define PH_OFF   27648
#define SF_OFF   36864
#define RL_OFF   54272
#define SM_ATT   55296

__global__ __launch_bounds__(256) void attn_wmma(float* __restrict__ out) {
    extern __shared__ char smem[];
    __half* Qh = (__half*)(smem + QH_OFF);
    __half* Kh = (__half*)(smem + KH_OFF);
    __half* Vh = (__half*)(smem + VH_OFF);
    __half* Ph = (__half*)(smem + PH_OFF);
    float*  Sf = (float*)(smem + SF_OFF);
    float*  redl = (float*)(smem + RL_OFF);
    float*  wot_s = (float*)(smem + QH_OFF);

    int t0   = blockIdx.x * 64;
    int b    = blockIdx.y;
    int tid  = threadIdx.x;
    int wid  = tid >> 5;
    int q    = tid & 63;
    int part = tid >> 6;
    int cb   = part * 16;
    int warp_m = wid & 3;
    int warp_n = wid >> 2;

    for (int j = tid; j < 4096; j += 256) {
        int tl = j >> 6, c = j & 63;
        int t = t0 + tl;
        Qh[tl * 72 + c] = (t < TOUT) ? d_qh[((size_t)b * TOUT + t) * CO + c]
                                     : __float2half(0.f);
    }

    wmma::fragment<wmma::accumulator, 16, 16, 16, float> ctx[2];
    #pragma unroll
    for (int j = 0; j < 2; j++) wmma::fill_fragment(ctx[j], 0.f);

    float l = 0.f;

    for (int stile = 0; stile < 10; stile++) {
        int s0 = stile * 64;
        __syncthreads();

        for (int j = tid; j < 4096; j += 256) {
            int c = j >> 6, sl = j & 63;
            int s = s0 + sl;
            Kh[c * 72 + sl] = (s < TOUT) ? d_kh[((size_t)b * CO + c) * TOUT + s]
                                         : __float2half(0.f);
        }
        for (int j = tid; j < 4096; j += 256) {
            int sl = j >> 6, c = j & 63;
            int s = s0 + sl;
            Vh[sl * 72 + c] = (s < TOUT) ? d_vh[((size_t)b * TOUT + s) * CO + c]
                                         : __float2half(0.f);
        }
        __syncthreads();

        {
            wmma::fragment<wmma::accumulator, 16, 16, 16, float> sacc[2];
            #pragma unroll
            for (int j = 0; j < 2; j++) wmma::fill_fragment(sacc[j], 0.f);
            #pragma unroll
            for (int kk = 0; kk < 4; kk++) {
                wmma::fragment<wmma::matrix_a, 16, 16, 16, __half, wmma::row_major> af;
                wmma::fragment<wmma::matrix_b, 16, 16, 16, __half, wmma::row_major> bf[2];
                wmma::load_matrix_sync(af, Qh + (warp_m * 16) * 72 + kk * 16, 72);
                #pragma unroll
                for (int j = 0; j < 2; j++)
                    wmma::load_matrix_sync(bf[j], Kh + (kk * 16) * 72 + warp_n * 32 + j * 16, 72);
                #pragma unroll
                for (int j = 0; j < 2; j++)
                    wmma::mma_sync(sacc[j], af, bf[j], sacc[j]);
            }
            #pragma unroll
            for (int j = 0; j < 2; j++)
                wmma::store_matrix_sync(Sf + (warp_m * 16) * 68 + warp_n * 32 + j * 16,
                                        sacc[j], 68, wmma::mem_row_major);
        }
        __syncthreads();

        {
            float lp = 0.f;
            const float4* sr = (const float4*)&Sf[q * 68 + cb];
            float4 s4[4] = { sr[0], sr[1], sr[2], sr[3] };
            float sv[16] = { s4[0].x, s4[0].y, s4[0].z, s4[0].w,
                             s4[1].x, s4[1].y, s4[1].z, s4[1].w,
                             s4[2].x, s4[2].y, s4[2].z, s4[2].w,
                             s4[3].x, s4[3].y, s4[3].z, s4[3].w };
            #pragma unroll
            for (int i = 0; i < 16; i++) {
                int sg = s0 + cb + i;
                float p = (sg < TOUT) ? __expf(sv[i] * 0.125f) : 0.f;
                Ph[q * 72 + cb + i] = __float2half(p);
                lp += p;
            }
            redl[part * 64 + q] = lp;
        }
        __syncthreads();

        l += redl[q] + redl[64 + q] + redl[128 + q] + redl[192 + q];

        #pragma unroll
        for (int kk = 0; kk < 4; kk++) {
            wmma::fragment<wmma::matrix_a, 16, 16, 16, __half, wmma::row_major> af;
            wmma::fragment<wmma::matrix_b, 16, 16, 16, __half, wmma::row_major> bf[2];
            wmma::load_matrix_sync(af, Ph + (warp_m * 16) * 72 + kk * 16, 72);
            #pragma unroll
            for (int j = 0; j < 2; j++)
                wmma::load_matrix_sync(bf[j], Vh + (kk * 16) * 72 + warp_n * 32 + j * 16, 72);
            #pragma unroll
            for (int j = 0; j < 2; j++)
                wmma::mma_sync(ctx[j], af, bf[j], ctx[j]);
        }
    }

    __syncthreads();
    #pragma unroll
    for (int j = 0; j < 2; j++)
        wmma::store_matrix_sync(Sf + (warp_m * 16) * 68 + warp_n * 32 + j * 16,
                                ctx[j], 68, wmma::mem_row_major);
    for (int j = tid; j < 4096; j += 256) wot_s[j] = d_wot[j];
    __syncthreads();

    float invl = 1.f / l;
    float ob[16];
    #pragma unroll
    for (int i = 0; i < 16; i++) ob[i] = 0.f;
    for (int c = 0; c < CO; c++) {
        float cv = Sf[q * 68 + c] * invl;
        const float4* wr = (const float4*)&wot_s[c * 64 + cb];
        float4 w0 = wr[0], w1 = wr[1], w2 = wr[2], w3 = wr[3];
        ob[0]  = fmaf(cv, w0.x, ob[0]);  ob[1]  = fmaf(cv, w0.y, ob[1]);
        ob[2]  = fmaf(cv, w0.z, ob[2]);  ob[3]  = fmaf(cv, w0.w, ob[3]);
        ob[4]  = fmaf(cv, w1.x, ob[4]);  ob[5]  = fmaf(cv, w1.y, ob[5]);
        ob[6]  = fmaf(cv, w1.z, ob[6]);  ob[7]  = fmaf(cv, w1.w, ob[7]);
        ob[8]  = fmaf(cv, w2.x, ob[8]);  ob[9]  = fmaf(cv, w2.y, ob[9]);
        ob[10] = fmaf(cv, w2.z, ob[10]); ob[11] = fmaf(cv, w2.w, ob[11]);
        ob[12] = fmaf(cv, w3.x, ob[12]); ob[13] = fmaf(cv, w3.y, ob[13]);
        ob[14] = fmaf(cv, w3.z, ob[14]); ob[15] = fmaf(cv, w3.w, ob[15]);
    }

    int t = t0 + q;
    if (t < TOUT) {
        #pragma unroll
        for (int i = 0; i < 16; i++) {
            int o = cb + i;
            out[((size_t)b * CO + o) * TOUT + t] =
                d_y[((size_t)b * CO + o) * TOUT + t] + ob[i];
        }
    }
}

// ---------------- launch ----------------
extern "C" void kernel_launch(void* const* d_in, const int* in_sizes, int n_in,
                              void* d_out, int out_size) {
    const float* x      = (const float*)d_in[0];
    const float* conv_w = (const float*)d_in[1];
    const float* conv_b = (const float*)d_in[2];
    const float* gamma  = (const float*)d_in[3];
    const float* beta   = (const float*)d_in[4];
    const float* mean   = (const float*)d_in[5];
    const float* var    = (const float*)d_in[6];
    const float* wq     = (const float*)d_in[7];
    const float* wk     = (const float*)d_in[8];
    const float* wv     = (const float*)d_in[9];
    const float* wo     = (const float*)d_in[10];
    float* out = (float*)d_out;

    prep_weights<<<64, 256>>>(conv_w, conv_b, gamma, beta, mean, var);
    prep_misc<<<1, 256>>>(wq, wk, wv, wo);

    cudaFuncSetAttribute(conv_wmma, cudaFuncAttributeMaxDynamicSharedMemorySize, SM_CONV);
    conv_wmma<<<dim3(5, NB), 256, SM_CONV>>>(x);

    cudaFuncSetAttribute(qkv_gemm, cudaFuncAttributeMaxDynamicSharedMemorySize, SM_QKV);
    qkv_gemm<<<dim3(10, NB), 256, SM_QKV>>>();

    cudaFuncSetAttribute(attn_wmma, cudaFuncAttributeMaxDynamicSharedMemorySize, SM_ATT);
    attn_wmma<<<dim3(10, NB), 256, SM_ATT>>>(out);
}

// round 12
// speedup vs baseline: 2.5811x; 1.5275x over previous
#include <cuda_runtime.h>
#include <cuda_fp16.h>
#include <mma.h>
#include <math.h>
#include <stdint.h>

using namespace nvcuda;

#define NB   128
#define CIN  128
#define TIN  2500
#define CO   64
#define KW   27
#define TOUT 625
#define KTOT (CIN * KW)      // 3456
#define NKB2 54              // chunks of 64 K

// ---------------- scratch (device globals; no allocation) ----------------
__device__ __half d_wh[KTOT * 64];            // sign rows [K][o]
__device__ unsigned long long d_ktab64[NKB2 * 8];  // per-K byte: (s<<6)|(r<<4)|a
__device__ float  d_scale[CO];
__device__ float  d_shift[CO];
__device__ float  d_y [NB * CO * TOUT];
__device__ __half d_qh[NB * TOUT * CO];       // (B,T,C)
__device__ __half d_kh[NB * CO * TOUT];       // (B,C,T)
__device__ __half d_vh[NB * TOUT * CO];       // (B,T,C)
__device__ __half d_wqkvh[192 * 128];
__device__ float  d_wot[CO * CO];

// ---------------- prep ----------------
__global__ void prep_weights(const float* __restrict__ w,
                             const float* __restrict__ cb,
                             const float* __restrict__ gamma,
                             const float* __restrict__ beta,
                             const float* __restrict__ mean,
                             const float* __restrict__ var) {
    int o = blockIdx.x;
    __shared__ float red[256];
    const float* wrow = w + o * KTOT;
    float s = 0.f;
    for (int j = threadIdx.x; j < KTOT; j += 256) s += fabsf(wrow[j]);
    red[threadIdx.x] = s;
    __syncthreads();
    for (int st = 128; st > 0; st >>= 1) {
        if (threadIdx.x < st) red[threadIdx.x] += red[threadIdx.x + st];
        __syncthreads();
    }
    float alpha = red[0] * (1.f / KTOT);
    float g = gamma[o] * rsqrtf(var[o] + 1e-5f);
    if (threadIdx.x == 0) {
        d_scale[o] = alpha * g;
        d_shift[o] = (cb[o] - mean[o]) * g + beta[o];
    }
    for (int K = threadIdx.x; K < KTOT; K += 256) {
        float wv = wrow[K];
        float sg = (wv > 0.f) ? 1.f : ((wv < 0.f) ? -1.f : 0.f);
        d_wh[K * 64 + o] = __float2half(sg);
    }
}

__global__ void prep_misc(const float* __restrict__ wq, const float* __restrict__ wk,
                          const float* __restrict__ wv, const float* __restrict__ wo) {
    for (int j = threadIdx.x; j < CO * CO; j += 256) {
        int o = j >> 6, c = j & 63;
        d_wot[c * CO + o] = wo[j];
    }
    for (int j = threadIdx.x; j < 192 * 128; j += 256) {
        int m = j >> 7, k = j & 127;
        float v = 0.f;
        if (m < 64)        { if (k < 64)  v = wq[m * 64 + k]; }
        else if (m < 128)  { if (k < 64)  v = wk[(m - 64) * 64 + k]; }
        else               { if (k >= 64) v = wv[(m - 128) * 64 + (k - 64)]; }
        d_wqkvh[j] = __float2half(v);
    }
    for (int K = threadIdx.x; K < KTOT; K += 256) {
        int ib = K >> 6, e = K & 63;
        int ci = K / 27, k = K - 27 * ci;
        int s  = ci - (64 * ib) / 27;        // 0..3
        ((uint8_t*)d_ktab64)[ib * 64 + e] =
            (uint8_t)((s << 6) | ((k & 3) << 4) | (k >> 2));
    }
}

// ---------------- wmma fp16 implicit-GEMM conv + BN + ELU ----------------
// grid (10, 128): M=64 t, N=64 co, 54 chunks of 64 K. Single-buffered, 23KB smem,
// high occupancy (~8 CTA/SM) provides the gather/build <-> MMA overlap.
#define CALD  72
#define CA_OFF 4608                 // window: 4*288 floats = 4608 B at 0
#define CB_OFF (CA_OFF + 9216)     // A: 64*72 half = 9216
#define SM_CONV (CB_OFF + 9216)    // + B: 64*72 half = 9216 -> 23040

__global__ __launch_bounds__(256) void conv_wmma(const float* __restrict__ x) {
    extern __shared__ char smem[];
    float*  W  = (float*)smem;                  // [slot][r][a]: slot*288 + r*72 + a
    __half* A  = (__half*)(smem + CA_OFF);      // [t][k] t<64, k<64, ld 72
    __half* Bs = (__half*)(smem + CB_OFF);      // [k][o] k<64, o<64, ld 72
    float*  Cs = (float*)smem;                  // epilogue alias 64x68 f32

    int tid = threadIdx.x, wid = tid >> 5, lid = tid & 31;
    int t0 = blockIdx.x * 64;
    int b  = blockIdx.y;
    int warp_m = wid & 3;          // 16 t-rows
    int warp_n = wid >> 2;         // 32 o-cols
    int w0 = 4 * t0 - 13;

    const float* xb = x + (size_t)b * CIN * TIN;

    wmma::fragment<wmma::accumulator, 16, 16, 16, float> acc[2];
    #pragma unroll
    for (int j = 0; j < 2; j++) wmma::fill_fragment(acc[j], 0.f);

    for (int ib = 0; ib < NKB2; ib++) {
        __syncthreads();                         // prior MMA done before overwrite

        // ---- window load (<=4 ci rows, contiguous, stored transposed-by-residue)
        int ci0 = (64 * ib) / 27;
        for (int j2 = tid; j2 < 1152; j2 += 256) {
            int slot = j2 / 288, j = j2 - slot * 288;
            int ci = ci0 + slot, gp = w0 + j;
            float v = 0.f;
            if (j < 279 && ci < CIN && (unsigned)gp < (unsigned)TIN)
                v = __ldg(xb + ci * TIN + gp);
            W[slot * 288 + (j & 3) * 72 + (j >> 2)] = v;
        }
        // ---- B copy: contiguous 8KB sign tile
        {
            const int4* bsrc = (const int4*)(d_wh + ib * 4096);
            #pragma unroll
            for (int e = 0; e < 2; e++) {
                int idx = tid + e * 256;
                int r = idx >> 3, sg = idx & 7;
                *(int4*)&Bs[r * CALD + sg * 8] = __ldg(bsrc + idx);
            }
        }
        __syncthreads();                         // window + B visible

        // ---- A build: warp wid owns K-cols wid*8..+7
        {
            unsigned long long pk8 = d_ktab64[ib * 8 + wid];
            int off[8];
            #pragma unroll
            for (int e = 0; e < 8; e++) {
                int pk = (int)((pk8 >> (8 * e)) & 255ull);
                off[e] = (pk >> 6) * 288 + ((pk >> 4) & 3) * 72 + (pk & 15);
            }
            #pragma unroll
            for (int p = 0; p < 2; p++) {
                int t = lid + p * 32;
                __half2 h2[4];
                #pragma unroll
                for (int q = 0; q < 4; q++)
                    h2[q] = __floats2half2_rn(W[off[2 * q] + t], W[off[2 * q + 1] + t]);
                int4 pack;
                pack.x = *(int*)&h2[0]; pack.y = *(int*)&h2[1];
                pack.z = *(int*)&h2[2]; pack.w = *(int*)&h2[3];
                *(int4*)&A[t * CALD + wid * 8] = pack;
            }
        }
        __syncthreads();                         // A ready

        // ---- MMA: 64x64x64
        #pragma unroll
        for (int kk = 0; kk < 4; kk++) {
            wmma::fragment<wmma::matrix_a, 16, 16, 16, __half, wmma::row_major> af;
            wmma::fragment<wmma::matrix_b, 16, 16, 16, __half, wmma::row_major> bf[2];
            wmma::load_matrix_sync(af, A + (warp_m * 16) * CALD + kk * 16, CALD);
            #pragma unroll
            for (int j = 0; j < 2; j++)
                wmma::load_matrix_sync(bf[j], Bs + (kk * 16) * CALD + warp_n * 32 + j * 16, CALD);
            #pragma unroll
            for (int j = 0; j < 2; j++)
                wmma::mma_sync(acc[j], af, bf[j], acc[j]);
        }
    }
    __syncthreads();                             // all MMA done before Cs alias

    #pragma unroll
    for (int j = 0; j < 2; j++)
        wmma::store_matrix_sync(Cs + (warp_m * 16) * 68 + warp_n * 32 + j * 16,
                                acc[j], 68, wmma::mem_row_major);
    __syncthreads();

    #pragma unroll
    for (int it = 0; it < 16; it++) {
        int idx = it * 256 + tid;
        int o  = idx >> 6;
        int tl = idx & 63;
        int t  = t0 + tl;
        if (t < TOUT) {
            float v = Cs[tl * 68 + o] * __ldg(d_scale + o) + __ldg(d_shift + o);
            v = (v > 0.f) ? v : expm1f(v);
            d_y[((size_t)b * CO + o) * TOUT + t] = v;
        }
    }
}

// ---------------- qkv as one wmma GEMM: [192x128] x [128x64] ----------------
#define BLD  72
#define QB_OFF 0
#define QA_OFF 18432
#define QC_OFF 18432
#define SM_QKV (18432 + 52224)

__global__ __launch_bounds__(256) void qkv_gemm() {
    extern __shared__ char smem[];
    __half* Bh = (__half*)(smem + QB_OFF);
    __half* Ah = (__half*)(smem + QA_OFF);
    float*  Cs = (float*)(smem + QC_OFF);

    int t0  = blockIdx.x * 64;
    int b   = blockIdx.y;
    int tid = threadIdx.x;
    int wid = tid >> 5;
    int warp_m = wid & 3;
    int warp_n = wid >> 2;

    for (int j = tid; j < 4096; j += 256) {
        int c = j >> 6, tl = j & 63;
        int t = t0 + tl;
        float yv = (t < TOUT) ? d_y[((size_t)b * CO + c) * TOUT + t] : 0.f;
        Bh[c * BLD + tl]        = __float2half(yv > 0.f ? 1.f : 0.f);
        Bh[(64 + c) * BLD + tl] = __float2half(yv);
    }
    {
        const int4* asrc = (const int4*)d_wqkvh;
        #pragma unroll
        for (int e = 0; e < 12; e++) {
            int idx = tid + e * 256;
            int m = idx >> 4, seg = idx & 15;
            *(int4*)&Ah[m * 136 + seg * 8] = __ldg(asrc + idx);
        }
    }
    __syncthreads();

    wmma::fragment<wmma::accumulator, 16, 16, 16, float> acc[3][2];
    #pragma unroll
    for (int i = 0; i < 3; i++)
        #pragma unroll
        for (int j = 0; j < 2; j++) wmma::fill_fragment(acc[i][j], 0.f);

    #pragma unroll
    for (int kk = 0; kk < 8; kk++) {
        wmma::fragment<wmma::matrix_a, 16, 16, 16, __half, wmma::row_major> af[3];
        wmma::fragment<wmma::matrix_b, 16, 16, 16, __half, wmma::row_major> bf[2];
        #pragma unroll
        for (int i = 0; i < 3; i++)
            wmma::load_matrix_sync(af[i], Ah + (warp_m * 48 + i * 16) * 136 + kk * 16, 136);
        #pragma unroll
        for (int j = 0; j < 2; j++)
            wmma::load_matrix_sync(bf[j], Bh + (kk * 16) * BLD + warp_n * 32 + j * 16, BLD);
        #pragma unroll
        for (int i = 0; i < 3; i++)
            #pragma unroll
            for (int j = 0; j < 2; j++)
                wmma::mma_sync(acc[i][j], af[i], bf[j], acc[i][j]);
    }
    __syncthreads();

    #pragma unroll
    for (int i = 0; i < 3; i++)
        #pragma unroll
        for (int j = 0; j < 2; j++)
            wmma::store_matrix_sync(Cs + (warp_m * 48 + i * 16) * 68 + warp_n * 32 + j * 16,
                                    acc[i][j], 68, wmma::mem_row_major);
    __syncthreads();

    for (int j = tid; j < 4096; j += 256) {
        int tl = j >> 6, o = j & 63;
        int t = t0 + tl;
        if (t < TOUT) d_qh[((size_t)b * TOUT + t) * CO + o] = __float2half(Cs[o * 68 + tl]);
    }
    for (int j = tid; j < 4096; j += 256) {
        int o = j >> 6, tl = j & 63;
        int t = t0 + tl;
        if (t < TOUT) d_kh[((size_t)b * CO + o) * TOUT + t] = __float2half(Cs[(64 + o) * 68 + tl]);
    }
    for (int j = tid; j < 4096; j += 256) {
        int tl = j >> 6, o = j & 63;
        int t = t0 + tl;
        if (t < TOUT) d_vh[((size_t)b * TOUT + t) * CO + o] = __float2half(Cs[(128 + o) * 68 + tl]);
    }
}

// ---------------- wmma attention (fixed-shift softmax) + wo + residual ----------------
#define QH_OFF   0
#define KH_OFF   9216
#define VH_OFF   18432
#define PH_OFF   27648
#define SF_OFF   36864
#define RL_OFF   54272
#define SM_ATT   55296

__global__ __launch_bounds__(256) void attn_wmma(float* __restrict__ out) {
    extern __shared__ char smem[];
    __half* Qh = (__half*)(smem + QH_OFF);
    __half* Kh = (__half*)(smem + KH_OFF);
    __half* Vh = (__half*)(smem + VH_OFF);
    __half* Ph = (__half*)(smem + PH_OFF);
    float*  Sf = (float*)(smem + SF_OFF);
    float*  redl = (float*)(smem + RL_OFF);
    float*  wot_s = (float*)(smem + QH_OFF);

    int t0   = blockIdx.x * 64;
    int b    = blockIdx.y;
    int tid  = threadIdx.x;
    int wid  = tid >> 5;
    int q    = tid & 63;
    int part = tid >> 6;
    int cb   = part * 16;
    int warp_m = wid & 3;
    int warp_n = wid >> 2;

    for (int j = tid; j < 4096; j += 256) {
        int tl = j >> 6, c = j & 63;
        int t = t0 + tl;
        Qh[tl * 72 + c] = (t < TOUT) ? d_qh[((size_t)b * TOUT + t) * CO + c]
                                     : __float2half(0.f);
    }

    wmma::fragment<wmma::accumulator, 16, 16, 16, float> ctx[2];
    #pragma unroll
    for (int j = 0; j < 2; j++) wmma::fill_fragment(ctx[j], 0.f);

    float l = 0.f;

    for (int stile = 0; stile < 10; stile++) {
        int s0 = stile * 64;
        __syncthreads();

        for (int j = tid; j < 4096; j += 256) {
            int c = j >> 6, sl = j & 63;
            int s = s0 + sl;
            Kh[c * 72 + sl] = (s < TOUT) ? d_kh[((size_t)b * CO + c) * TOUT + s]
                                         : __float2half(0.f);
        }
        for (int j = tid; j < 4096; j += 256) {
            int sl = j >> 6, c = j & 63;
            int s = s0 + sl;
            Vh[sl * 72 + c] = (s < TOUT) ? d_vh[((size_t)b * TOUT + s) * CO + c]
                                         : __float2half(0.f);
        }
        __syncthreads();

        {
            wmma::fragment<wmma::accumulator, 16, 16, 16, float> sacc[2];
            #pragma unroll
            for (int j = 0; j < 2; j++) wmma::fill_fragment(sacc[j], 0.f);
            #pragma unroll
            for (int kk = 0; kk < 4; kk++) {
                wmma::fragment<wmma::matrix_a, 16, 16, 16, __half, wmma::row_major> af;
                wmma::fragment<wmma::matrix_b, 16, 16, 16, __half, wmma::row_major> bf[2];
                wmma::load_matrix_sync(af, Qh + (warp_m * 16) * 72 + kk * 16, 72);
                #pragma unroll
                for (int j = 0; j < 2; j++)
                    wmma::load_matrix_sync(bf[j], Kh + (kk * 16) * 72 + warp_n * 32 + j * 16, 72);
                #pragma unroll
                for (int j = 0; j < 2; j++)
                    wmma::mma_sync(sacc[j], af, bf[j], sacc[j]);
            }
            #pragma unroll
            for (int j = 0; j < 2; j++)
                wmma::store_matrix_sync(Sf + (warp_m * 16) * 68 + warp_n * 32 + j * 16,
                                        sacc[j], 68, wmma::mem_row_major);
        }
        __syncthreads();

        {
            float lp = 0.f;
            const float4* sr = (const float4*)&Sf[q * 68 + cb];
            float4 s4[4] = { sr[0], sr[1], sr[2], sr[3] };
            float sv[16] = { s4[0].x, s4[0].y, s4[0].z, s4[0].w,
                             s4[1].x, s4[1].y, s4[1].z, s4[1].w,
                             s4[2].x, s4[2].y, s4[2].z, s4[2].w,
                             s4[3].x, s4[3].y, s4[3].z, s4[3].w };
            #pragma unroll
            for (int i = 0; i < 16; i++) {
                int sg = s0 + cb + i;
                float p = (sg < TOUT) ? __expf(sv[i] * 0.125f) : 0.f;
                Ph[q * 72 + cb + i] = __float2half(p);
                lp += p;
            }
            redl[part * 64 + q] = lp;
        }
        __syncthreads();

        l += redl[q] + redl[64 + q] + redl[128 + q] + redl[192 + q];

        #pragma unroll
        for (int kk = 0; kk < 4; kk++) {
            wmma::fragment<wmma::matrix_a, 16, 16, 16, __half, wmma::row_major> af;
            wmma::fragment<wmma::matrix_b, 16, 16, 16, __half, wmma::row_major> bf[2];
            wmma::load_matrix_sync(af, Ph + (warp_m * 16) * 72 + kk * 16, 72);
            #pragma unroll
            for (int j = 0; j < 2; j++)
                wmma::load_matrix_sync(bf[j], Vh + (kk * 16) * 72 + warp_n * 32 + j * 16, 72);
            #pragma unroll
            for (int j = 0; j < 2; j++)
                wmma::mma_sync(ctx[j], af, bf[j], ctx[j]);
        }
    }

    __syncthreads();
    #pragma unroll
    for (int j = 0; j < 2; j++)
        wmma::store_matrix_sync(Sf + (warp_m * 16) * 68 + warp_n * 32 + j * 16,
                                ctx[j], 68, wmma::mem_row_major);
    for (int j = tid; j < 4096; j += 256) wot_s[j] = d_wot[j];
    __syncthreads();

    float invl = 1.f / l;
    float ob[16];
    #pragma unroll
    for (int i = 0; i < 16; i++) ob[i] = 0.f;
    for (int c = 0; c < CO; c++) {
        float cv = Sf[q * 68 + c] * invl;
        const float4* wr = (const float4*)&wot_s[c * 64 + cb];
        float4 w0 = wr[0], w1 = wr[1], w2 = wr[2], w3 = wr[3];
        ob[0]  = fmaf(cv, w0.x, ob[0]);  ob[1]  = fmaf(cv, w0.y, ob[1]);
        ob[2]  = fmaf(cv, w0.z, ob[2]);  ob[3]  = fmaf(cv, w0.w, ob[3]);
        ob[4]  = fmaf(cv, w1.x, ob[4]);  ob[5]  = fmaf(cv, w1.y, ob[5]);
        ob[6]  = fmaf(cv, w1.z, ob[6]);  ob[7]  = fmaf(cv, w1.w, ob[7]);
        ob[8]  = fmaf(cv, w2.x, ob[8]);  ob[9]  = fmaf(cv, w2.y, ob[9]);
        ob[10] = fmaf(cv, w2.z, ob[10]); ob[11] = fmaf(cv, w2.w, ob[11]);
        ob[12] = fmaf(cv, w3.x, ob[12]); ob[13] = fmaf(cv, w3.y, ob[13]);
        ob[14] = fmaf(cv, w3.z, ob[14]); ob[15] = fmaf(cv, w3.w, ob[15]);
    }

    int t = t0 + q;
    if (t < TOUT) {
        #pragma unroll
        for (int i = 0; i < 16; i++) {
            int o = cb + i;
            out[((size_t)b * CO + o) * TOUT + t] =
                d_y[((size_t)b * CO + o) * TOUT + t] + ob[i];
        }
    }
}

// ---------------- launch ----------------
extern "C" void kernel_launch(void* const* d_in, const int* in_sizes, int n_in,
                              void* d_out, int out_size) {
    const float* x      = (const float*)d_in[0];
    const float* conv_w = (const float*)d_in[1];
    const float* conv_b = (const float*)d_in[2];
    const float* gamma  = (const float*)d_in[3];
    const float* beta   = (const float*)d_in[4];
    const float* mean   = (const float*)d_in[5];
    const float* var    = (const float*)d_in[6];
    const float* wq     = (const float*)d_in[7];
    const float* wk     = (const float*)d_in[8];
    const float* wv     = (const float*)d_in[9];
    const float* wo     = (const float*)d_in[10];
    float* out = (float*)d_out;

    prep_weights<<<64, 256>>>(conv_w, conv_b, gamma, beta, mean, var);
    prep_misc<<<1, 256>>>(wq, wk, wv, wo);

    cudaFuncSetAttribute(conv_wmma, cudaFuncAttributeMaxDynamicSharedMemorySize, SM_CONV);
    conv_wmma<<<dim3(10, NB), 256, SM_CONV>>>(x);

    cudaFuncSetAttribute(qkv_gemm, cudaFuncAttributeMaxDynamicSharedMemorySize, SM_QKV);
    qkv_gemm<<<dim3(10, NB), 256, SM_QKV>>>();

    cudaFuncSetAttribute(attn_wmma, cudaFuncAttributeMaxDynamicSharedMemorySize, SM_ATT);
    attn_wmma<<<dim3(10, NB), 256, SM_ATT>>>(out);
}

// round 14
// speedup vs baseline: 3.1375x; 1.2156x over previous
#include <cuda_runtime.h>
#include <cuda_fp16.h>
#include <mma.h>
#include <math.h>
#include <stdint.h>

using namespace nvcuda;

#define NB   128
#define CIN  128
#define TIN  2500
#define CO   64
#define KW   27
#define TOUT 625
#define KTOT (CIN * KW)      // 3456
#define NKB2 54              // chunks of 64 K

// ---------------- scratch (device globals; no allocation) ----------------
__device__ __half d_wh[KTOT * 64];            // sign rows [K][o]
__device__ unsigned long long d_ktab64[NKB2 * 8];  // per-K byte: (s<<6)|(r<<4)|a
__device__ float  d_scale[CO];
__device__ float  d_shift[CO];
__device__ float  d_y [NB * CO * TOUT];
__device__ __half d_qh[NB * TOUT * CO];       // (B,T,C)
__device__ __half d_kh[NB * CO * TOUT];       // (B,C,T)
__device__ __half d_vh[NB * TOUT * CO];       // (B,T,C)
__device__ __half d_wqkvh[192 * 128];
__device__ float  d_wot[CO * CO];

__device__ __forceinline__ uint32_t smem_u32(const void* p) {
    uint32_t a;
    asm("{ .reg .u64 t; cvta.to.shared.u64 t, %1; cvt.u32.u64 %0, t; }" : "=r"(a) : "l"(p));
    return a;
}
__device__ __forceinline__ void mma16816(float* c, uint32_t a0, uint32_t a1,
                                         uint32_t a2, uint32_t a3,
                                         uint32_t b0, uint32_t b1) {
    asm volatile(
        "mma.sync.aligned.m16n8k16.row.col.f32.f16.f16.f32 "
        "{%0,%1,%2,%3}, {%4,%5,%6,%7}, {%8,%9}, {%0,%1,%2,%3};"
        : "+f"(c[0]), "+f"(c[1]), "+f"(c[2]), "+f"(c[3])
        : "r"(a0), "r"(a1), "r"(a2), "r"(a3), "r"(b0), "r"(b1));
}

// ---------------- prep ----------------
__global__ void prep_weights(const float* __restrict__ w,
                             const float* __restrict__ cb,
                             const float* __restrict__ gamma,
                             const float* __restrict__ beta,
                             const float* __restrict__ mean,
                             const float* __restrict__ var) {
    int o = blockIdx.x;
    __shared__ float red[256];
    const float* wrow = w + o * KTOT;
    float s = 0.f;
    for (int j = threadIdx.x; j < KTOT; j += 256) s += fabsf(wrow[j]);
    red[threadIdx.x] = s;
    __syncthreads();
    for (int st = 128; st > 0; st >>= 1) {
        if (threadIdx.x < st) red[threadIdx.x] += red[threadIdx.x + st];
        __syncthreads();
    }
    float alpha = red[0] * (1.f / KTOT);
    float g = gamma[o] * rsqrtf(var[o] + 1e-5f);
    if (threadIdx.x == 0) {
        d_scale[o] = alpha * g;
        d_shift[o] = (cb[o] - mean[o]) * g + beta[o];
    }
    for (int K = threadIdx.x; K < KTOT; K += 256) {
        float wv = wrow[K];
        float sg = (wv > 0.f) ? 1.f : ((wv < 0.f) ? -1.f : 0.f);
        d_wh[K * 64 + o] = __float2half(sg);
    }
}

__global__ void prep_misc(const float* __restrict__ wq, const float* __restrict__ wk,
                          const float* __restrict__ wv, const float* __restrict__ wo) {
    int gtid = blockIdx.x * blockDim.x + threadIdx.x;
    int gstr = gridDim.x * blockDim.x;
    for (int j = gtid; j < CO * CO; j += gstr) {
        int o = j >> 6, c = j & 63;
        d_wot[c * CO + o] = wo[j];
    }
    for (int j = gtid; j < 192 * 128; j += gstr) {
        int m = j >> 7, k = j & 127;
        float v = 0.f;
        if (m < 64)        { if (k < 64)  v = wq[m * 64 + k]; }
        else if (m < 128)  { if (k < 64)  v = wk[(m - 64) * 64 + k]; }
        else               { if (k >= 64) v = wv[(m - 128) * 64 + (k - 64)]; }
        d_wqkvh[j] = __float2half(v);
    }
    for (int K = gtid; K < KTOT; K += gstr) {
        int ib = K >> 6, e = K & 63;
        int ci = K / 27, k = K - 27 * ci;
        int s  = ci - (64 * ib) / 27;        // 0..3
        ((uint8_t*)d_ktab64)[ib * 64 + e] =
            (uint8_t)((s << 6) | ((k & 3) << 4) | (k >> 2));
    }
}

// ---------------- raw-mma fp16 implicit-GEMM conv + BN + ELU ----------------
// grid (10, 128), 128 threads (4 warps). Warp w: rows t = w*16..+15, full N=64.
// A fragments built directly in registers from transposed window W (no A smem).
#define W_OFF    0                   // 1152 floats = 4608
#define KOFF_OFF 4608                // 64 ints = 256
#define CB_OFF   4864                // B: 64*72 half = 9216 -> 14080
#define SM_CONV  17664               // Cs alias 64*68*4 = 17408 at 0

__global__ __launch_bounds__(128) void conv_mma(const float* __restrict__ x) {
    extern __shared__ char smem[];
    float*  W      = (float*)(smem + W_OFF);     // [slot*288 + r*72 + a]
    int*    koff_s = (int*)(smem + KOFF_OFF);
    __half* Bs     = (__half*)(smem + CB_OFF);   // [k][o], ld 72
    float*  Cs     = (float*)smem;               // epilogue alias 64x68

    int tid = threadIdx.x, wid = tid >> 5, lid = tid & 31;
    int t0 = blockIdx.x * 64;
    int b  = blockIdx.y;
    int w0 = 4 * t0 - 13;

    const float* xb = x + (size_t)b * CIN * TIN;
    uint32_t Bbase = smem_u32(Bs);
    // ldmatrix lane address offsets (constant per lane): group g covers
    // m0..m3 = (k rows 0-7 / 8-15) x (n cols +0 / +8)
    int g  = lid >> 3, i5 = lid & 7;
    int lm_krow = i5 + (g & 1) * 8;
    int lm_ncol = (g >> 1) * 8;

    float acc[8][4];
    #pragma unroll
    for (int f = 0; f < 8; f++)
        #pragma unroll
        for (int j = 0; j < 4; j++) acc[f][j] = 0.f;

    int tA = wid * 16 + (lid >> 2);     // A row for this lane

    for (int ib = 0; ib < NKB2; ib++) {
        __syncthreads();                 // prior iter's reads done

        // window load (<=4 ci rows, contiguous, transposed-by-residue)
        int ci0 = (64 * ib) / 27;
        for (int j2 = tid; j2 < 1152; j2 += 128) {
            int slot = j2 / 288, j = j2 - slot * 288;
            int ci = ci0 + slot, gp = w0 + j;
            float v = 0.f;
            if (j < 279 && ci < CIN && (unsigned)gp < (unsigned)TIN)
                v = __ldg(xb + ci * TIN + gp);
            W[slot * 288 + (j & 3) * 72 + (j >> 2)] = v;
        }
        // B copy: contiguous 8KB sign tile
        {
            const int4* bsrc = (const int4*)(d_wh + ib * 4096);
            #pragma unroll
            for (int e = 0; e < 4; e++) {
                int idx = tid + e * 128;
                int r = idx >> 3, sg = idx & 7;
                *(int4*)&Bs[r * 72 + sg * 8] = __ldg(bsrc + idx);
            }
        }
        // koff decode
        if (tid < 64) {
            int pk = ((const uint8_t*)d_ktab64)[ib * 64 + tid];
            koff_s[tid] = (pk >> 6) * 288 + ((pk >> 4) & 3) * 72 + (pk & 15);
        }
        __syncthreads();                 // W/B/koff ready

        #pragma unroll
        for (int kk = 0; kk < 4; kk++) {
            // ---- A fragment direct from W
            int kb0 = kk * 16 + (lid & 3) * 2;
            int o0 = koff_s[kb0], o1 = koff_s[kb0 + 1];
            int o2 = koff_s[kb0 + 8], o3 = koff_s[kb0 + 9];
            __half2 h;
            uint32_t a0, a1, a2, a3;
            h = __floats2half2_rn(W[o0 + tA],     W[o1 + tA]);     a0 = *(uint32_t*)&h;
            h = __floats2half2_rn(W[o0 + tA + 8], W[o1 + tA + 8]); a1 = *(uint32_t*)&h;
            h = __floats2half2_rn(W[o2 + tA],     W[o3 + tA]);     a2 = *(uint32_t*)&h;
            h = __floats2half2_rn(W[o2 + tA + 8], W[o3 + tA + 8]); a3 = *(uint32_t*)&h;

            // ---- B fragments (2 n8 at a time) + mma
            #pragma unroll
            for (int np = 0; np < 4; np++) {
                uint32_t b0, b1, b2, b3;
                uint32_t baddr = Bbase +
                    (uint32_t)(((kk * 16 + lm_krow) * 72 + np * 16 + lm_ncol) * 2);
                asm volatile(
                    "ldmatrix.sync.aligned.m8n8.x4.trans.shared.b16 "
                    "{%0,%1,%2,%3}, [%4];"
                    : "=r"(b0), "=r"(b1), "=r"(b2), "=r"(b3) : "r"(baddr));
                mma16816(acc[np * 2],     a0, a1, a2, a3, b0, b1);
                mma16816(acc[np * 2 + 1], a0, a1, a2, a3, b2, b3);
            }
        }
    }
    __syncthreads();                     // all reads of W/Bs done before alias

    // accum -> Cs
    {
        int r = wid * 16 + (lid >> 2);
        int cb2 = (lid & 3) * 2;
        #pragma unroll
        for (int f = 0; f < 8; f++) {
            int c = f * 8 + cb2;
            Cs[r * 68 + c]           = acc[f][0];
            Cs[r * 68 + c + 1]       = acc[f][1];
            Cs[(r + 8) * 68 + c]     = acc[f][2];
            Cs[(r + 8) * 68 + c + 1] = acc[f][3];
        }
    }
    __syncthreads();

    #pragma unroll
    for (int it = 0; it < 32; it++) {
        int idx = it * 128 + tid;
        int o  = idx >> 6;
        int tl = idx & 63;
        int t  = t0 + tl;
        if (t < TOUT) {
            float v = Cs[tl * 68 + o] * __ldg(d_scale + o) + __ldg(d_shift + o);
            v = (v > 0.f) ? v : expm1f(v);
            d_y[((size_t)b * CO + o) * TOUT + t] = v;
        }
    }
}

// ---------------- qkv as one wmma GEMM: [192x128] x [128x64] ----------------
#define BLD  72
#define QB_OFF 0
#define QA_OFF 18432
#define QC_OFF 18432
#define SM_QKV (18432 + 52224)

__global__ __launch_bounds__(256) void qkv_gemm() {
    extern __shared__ char smem[];
    __half* Bh = (__half*)(smem + QB_OFF);
    __half* Ah = (__half*)(smem + QA_OFF);
    float*  Cs = (float*)(smem + QC_OFF);

    int t0  = blockIdx.x * 64;
    int b   = blockIdx.y;
    int tid = threadIdx.x;
    int wid = tid >> 5;
    int warp_m = wid & 3;
    int warp_n = wid >> 2;

    for (int j = tid; j < 4096; j += 256) {
        int c = j >> 6, tl = j & 63;
        int t = t0 + tl;
        float yv = (t < TOUT) ? d_y[((size_t)b * CO + c) * TOUT + t] : 0.f;
        Bh[c * BLD + tl]        = __float2half(yv > 0.f ? 1.f : 0.f);
        Bh[(64 + c) * BLD + tl] = __float2half(yv);
    }
    {
        const int4* asrc = (const int4*)d_wqkvh;
        #pragma unroll
        for (int e = 0; e < 12; e++) {
            int idx = tid + e * 256;
            int m = idx >> 4, seg = idx & 15;
            *(int4*)&Ah[m * 136 + seg * 8] = __ldg(asrc + idx);
        }
    }
    __syncthreads();

    wmma::fragment<wmma::accumulator, 16, 16, 16, float> acc[3][2];
    #pragma unroll
    for (int i = 0; i < 3; i++)
        #pragma unroll
        for (int j = 0; j < 2; j++) wmma::fill_fragment(acc[i][j], 0.f);

    #pragma unroll
    for (int kk = 0; kk < 8; kk++) {
        wmma::fragment<wmma::matrix_a, 16, 16, 16, __half, wmma::row_major> af[3];
        wmma::fragment<wmma::matrix_b, 16, 16, 16, __half, wmma::row_major> bf[2];
        #pragma unroll
        for (int i = 0; i < 3; i++)
            wmma::load_matrix_sync(af[i], Ah + (warp_m * 48 + i * 16) * 136 + kk * 16, 136);
        #pragma unroll
        for (int j = 0; j < 2; j++)
            wmma::load_matrix_sync(bf[j], Bh + (kk * 16) * BLD + warp_n * 32 + j * 16, BLD);
        #pragma unroll
        for (int i = 0; i < 3; i++)
            #pragma unroll
            for (int j = 0; j < 2; j++)
                wmma::mma_sync(acc[i][j], af[i], bf[j], acc[i][j]);
    }
    __syncthreads();

    #pragma unroll
    for (int i = 0; i < 3; i++)
        #pragma unroll
        for (int j = 0; j < 2; j++)
            wmma::store_matrix_sync(Cs + (warp_m * 48 + i * 16) * 68 + warp_n * 32 + j * 16,
                                    acc[i][j], 68, wmma::mem_row_major);
    __syncthreads();

    for (int j = tid; j < 4096; j += 256) {
        int tl = j >> 6, o = j & 63;
        int t = t0 + tl;
        if (t < TOUT) d_qh[((size_t)b * TOUT + t) * CO + o] = __float2half(Cs[o * 68 + tl]);
    }
    for (int j = tid; j < 4096; j += 256) {
        int o = j >> 6, tl = j & 63;
        int t = t0 + tl;
        if (t < TOUT) d_kh[((size_t)b * CO + o) * TOUT + t] = __float2half(Cs[(64 + o) * 68 + tl]);
    }
    for (int j = tid; j < 4096; j += 256) {
        int tl = j >> 6, o = j & 63;
        int t = t0 + tl;
        if (t < TOUT) d_vh[((size_t)b * TOUT + t) * CO + o] = __float2half(Cs[(128 + o) * 68 + tl]);
    }
}

// ---------------- wmma attention (fixed-shift softmax) + wo + residual ----------------
#define QH_OFF   0
#define KH_OFF   9216
#define VH_OFF   18432
#define PH_OFF   27648
#define SF_OFF   36864
#define RL_OFF   54272
#define SM_ATT   55296

__global__ __launch_bounds__(256) void attn_wmma(float* __restrict__ out) {
    extern __shared__ char smem[];
    __half* Qh = (__half*)(smem + QH_OFF);
    __half* Kh = (__half*)(smem + KH_OFF);
    __half* Vh = (__half*)(smem + VH_OFF);
    __half* Ph = (__half*)(smem + PH_OFF);
    float*  Sf = (float*)(smem + SF_OFF);
    float*  redl = (float*)(smem + RL_OFF);
    float*  wot_s = (float*)(smem + QH_OFF);

    int t0   = blockIdx.x * 64;
    int b    = blockIdx.y;
    int tid  = threadIdx.x;
    int wid  = tid >> 5;
    int q    = tid & 63;
    int part = tid >> 6;
    int cb   = part * 16;
    int warp_m = wid & 3;
    int warp_n = wid >> 2;

    for (int j = tid; j < 4096; j += 256) {
        int tl = j >> 6, c = j & 63;
        int t = t0 + tl;
        Qh[tl * 72 + c] = (t < TOUT) ? d_qh[((size_t)b * TOUT + t) * CO + c]
                                     : __float2half(0.f);
    }

    wmma::fragment<wmma::accumulator, 16, 16, 16, float> ctx[2];
    #pragma unroll
    for (int j = 0; j < 2; j++) wmma::fill_fragment(ctx[j], 0.f);

    float l = 0.f;

    for (int stile = 0; stile < 10; stile++) {
        int s0 = stile * 64;
        __syncthreads();

        for (int j = tid; j < 4096; j += 256) {
            int c = j >> 6, sl = j & 63;
            int s = s0 + sl;
            Kh[c * 72 + sl] = (s < TOUT) ? d_kh[((size_t)b * CO + c) * TOUT + s]
                                         : __float2half(0.f);
        }
        for (int j = tid; j < 4096; j += 256) {
            int sl = j >> 6, c = j & 63;
            int s = s0 + sl;
            Vh[sl * 72 + c] = (s < TOUT) ? d_vh[((size_t)b * TOUT + s) * CO + c]
                                         : __float2half(0.f);
        }
        __syncthreads();

        {
            wmma::fragment<wmma::accumulator, 16, 16, 16, float> sacc[2];
            #pragma unroll
            for (int j = 0; j < 2; j++) wmma::fill_fragment(sacc[j], 0.f);
            #pragma unroll
            for (int kk = 0; kk < 4; kk++) {
                wmma::fragment<wmma::matrix_a, 16, 16, 16, __half, wmma::row_major> af;
                wmma::fragment<wmma::matrix_b, 16, 16, 16, __half, wmma::row_major> bf[2];
                wmma::load_matrix_sync(af, Qh + (warp_m * 16) * 72 + kk * 16, 72);
                #pragma unroll
                for (int j = 0; j < 2; j++)
                    wmma::load_matrix_sync(bf[j], Kh + (kk * 16) * 72 + warp_n * 32 + j * 16, 72);
                #pragma unroll
                for (int j = 0; j < 2; j++)
                    wmma::mma_sync(sacc[j], af, bf[j], sacc[j]);
            }
            #pragma unroll
            for (int j = 0; j < 2; j++)
                wmma::store_matrix_sync(Sf + (warp_m * 16) * 68 + warp_n * 32 + j * 16,
                                        sacc[j], 68, wmma::mem_row_major);
        }
        __syncthreads();

        {
            float lp = 0.f;
            const float4* sr = (const float4*)&Sf[q * 68 + cb];
            float4 s4[4] = { sr[0], sr[1], sr[2], sr[3] };
            float sv[16] = { s4[0].x, s4[0].y, s4[0].z, s4[0].w,
                             s4[1].x, s4[1].y, s4[1].z, s4[1].w,
                             s4[2].x, s4[2].y, s4[2].z, s4[2].w,
                             s4[3].x, s4[3].y, s4[3].z, s4[3].w };
            #pragma unroll
            for (int i = 0; i < 16; i++) {
                int sg = s0 + cb + i;
                float p = (sg < TOUT) ? __expf(sv[i] * 0.125f) : 0.f;
                Ph[q * 72 + cb + i] = __float2half(p);
                lp += p;
            }
            redl[part * 64 + q] = lp;
        }
        __syncthreads();

        l += redl[q] + redl[64 + q] + redl[128 + q] + redl[192 + q];

        #pragma unroll
        for (int kk = 0; kk < 4; kk++) {
            wmma::fragment<wmma::matrix_a, 16, 16, 16, __half, wmma::row_major> af;
            wmma::fragment<wmma::matrix_b, 16, 16, 16, __half, wmma::row_major> bf[2];
            wmma::load_matrix_sync(af, Ph + (warp_m * 16) * 72 + kk * 16, 72);
            #pragma unroll
            for (int j = 0; j < 2; j++)
                wmma::load_matrix_sync(bf[j], Vh + (kk * 16) * 72 + warp_n * 32 + j * 16, 72);
            #pragma unroll
            for (int j = 0; j < 2; j++)
                wmma::mma_sync(ctx[j], af, bf[j], ctx[j]);
        }
    }

    __syncthreads();
    #pragma unroll
    for (int j = 0; j < 2; j++)
        wmma::store_matrix_sync(Sf + (warp_m * 16) * 68 + warp_n * 32 + j * 16,
                                ctx[j], 68, wmma::mem_row_major);
    for (int j = tid; j < 4096; j += 256) wot_s[j] = d_wot[j];
    __syncthreads();

    float invl = 1.f / l;
    float ob[16];
    #pragma unroll
    for (int i = 0; i < 16; i++) ob[i] = 0.f;
    for (int c = 0; c < CO; c++) {
        float cv = Sf[q * 68 + c] * invl;
        const float4* wr = (const float4*)&wot_s[c * 64 + cb];
        float4 w0 = wr[0], w1 = wr[1], w2 = wr[2], w3 = wr[3];
        ob[0]  = fmaf(cv, w0.x, ob[0]);  ob[1]  = fmaf(cv, w0.y, ob[1]);
        ob[2]  = fmaf(cv, w0.z, ob[2]);  ob[3]  = fmaf(cv, w0.w, ob[3]);
        ob[4]  = fmaf(cv, w1.x, ob[4]);  ob[5]  = fmaf(cv, w1.y, ob[5]);
        ob[6]  = fmaf(cv, w1.z, ob[6]);  ob[7]  = fmaf(cv, w1.w, ob[7]);
        ob[8]  = fmaf(cv, w2.x, ob[8]);  ob[9]  = fmaf(cv, w2.y, ob[9]);
        ob[10] = fmaf(cv, w2.z, ob[10]); ob[11] = fmaf(cv, w2.w, ob[11]);
        ob[12] = fmaf(cv, w3.x, ob[12]); ob[13] = fmaf(cv, w3.y, ob[13]);
        ob[14] = fmaf(cv, w3.z, ob[14]); ob[15] = fmaf(cv, w3.w, ob[15]);
    }

    int t = t0 + q;
    if (t < TOUT) {
        #pragma unroll
        for (int i = 0; i < 16; i++) {
            int o = cb + i;
            out[((size_t)b * CO + o) * TOUT + t] =
                d_y[((size_t)b * CO + o) * TOUT + t] + ob[i];
        }
    }
}

// ---------------- launch ----------------
extern "C" void kernel_launch(void* const* d_in, const int* in_sizes, int n_in,
                              void* d_out, int out_size) {
    const float* x      = (const float*)d_in[0];
    const float* conv_w = (const float*)d_in[1];
    const float* conv_b = (const float*)d_in[2];
    const float* gamma  = (const float*)d_in[3];
    const float* beta   = (const float*)d_in[4];
    const float* mean   = (const float*)d_in[5];
    const float* var    = (const float*)d_in[6];
    const float* wq     = (const float*)d_in[7];
    const float* wk     = (const float*)d_in[8];
    const float* wv     = (const float*)d_in[9];
    const float* wo     = (const float*)d_in[10];
    float* out = (float*)d_out;

    prep_weights<<<64, 256>>>(conv_w, conv_b, gamma, beta, mean, var);
    prep_misc<<<16, 256>>>(wq, wk, wv, wo);

    cudaFuncSetAttribute(conv_mma, cudaFuncAttributeMaxDynamicSharedMemorySize, SM_CONV);
    conv_mma<<<dim3(10, NB), 128, SM_CONV>>>(x);

    cudaFuncSetAttribute(qkv_gemm, cudaFuncAttributeMaxDynamicSharedMemorySize, SM_QKV);
    qkv_gemm<<<dim3(10, NB), 256, SM_QKV>>>();

    cudaFuncSetAttribute(attn_wmma, cudaFuncAttributeMaxDynamicSharedMemorySize, SM_ATT);
    attn_wmma<<<dim3(10, NB), 256, SM_ATT>>>(out);
}

// round 15
// speedup vs baseline: 3.6541x; 1.1647x over previous
#include <cuda_runtime.h>
#include <cuda_fp16.h>
#include <mma.h>
#include <math.h>
#include <stdint.h>

using namespace nvcuda;

#define NB   128
#define CIN  128
#define TIN  2500
#define CO   64
#define KW   27
#define TOUT 625
#define KTOT (CIN * KW)      // 3456
#define NKB2 54              // chunks of 64 K

// ---------------- scratch (device globals; no allocation) ----------------
__device__ __half d_wh[KTOT * 64];            // sign rows [K][o]
__device__ unsigned long long d_ktab64[NKB2 * 8];  // per-K byte: (s<<6)|(r<<4)|a
__device__ float  d_scale[CO];
__device__ float  d_shift[CO];
__device__ float  d_y [NB * CO * TOUT];
__device__ __half d_qh[NB * TOUT * CO];       // (B,T,C)
__device__ __half d_kh[NB * CO * TOUT];       // (B,C,T)
__device__ __half d_vh[NB * TOUT * CO];       // (B,T,C)
__device__ __half d_wqkvh[192 * 128];
__device__ float  d_wot[CO * CO];

__device__ __forceinline__ uint32_t smem_u32(const void* p) {
    uint32_t a;
    asm("{ .reg .u64 t; cvta.to.shared.u64 t, %1; cvt.u32.u64 %0, t; }" : "=r"(a) : "l"(p));
    return a;
}
__device__ __forceinline__ void mma16816(float* c, uint32_t a0, uint32_t a1,
                                         uint32_t a2, uint32_t a3,
                                         uint32_t b0, uint32_t b1) {
    asm volatile(
        "mma.sync.aligned.m16n8k16.row.col.f32.f16.f16.f32 "
        "{%0,%1,%2,%3}, {%4,%5,%6,%7}, {%8,%9}, {%0,%1,%2,%3};"
        : "+f"(c[0]), "+f"(c[1]), "+f"(c[2]), "+f"(c[3])
        : "r"(a0), "r"(a1), "r"(a2), "r"(a3), "r"(b0), "r"(b1));
}

// ---------------- prep ----------------
__global__ void prep_weights(const float* __restrict__ w,
                             const float* __restrict__ cb,
                             const float* __restrict__ gamma,
                             const float* __restrict__ beta,
                             const float* __restrict__ mean,
                             const float* __restrict__ var) {
    int o = blockIdx.x;
    __shared__ float red[256];
    const float* wrow = w + o * KTOT;
    float s = 0.f;
    for (int j = threadIdx.x; j < KTOT; j += 256) s += fabsf(wrow[j]);
    red[threadIdx.x] = s;
    __syncthreads();
    for (int st = 128; st > 0; st >>= 1) {
        if (threadIdx.x < st) red[threadIdx.x] += red[threadIdx.x + st];
        __syncthreads();
    }
    float alpha = red[0] * (1.f / KTOT);
    float g = gamma[o] * rsqrtf(var[o] + 1e-5f);
    if (threadIdx.x == 0) {
        d_scale[o] = alpha * g;
        d_shift[o] = (cb[o] - mean[o]) * g + beta[o];
    }
    for (int K = threadIdx.x; K < KTOT; K += 256) {
        float wv = wrow[K];
        float sg = (wv > 0.f) ? 1.f : ((wv < 0.f) ? -1.f : 0.f);
        d_wh[K * 64 + o] = __float2half(sg);
    }
}

__global__ void prep_misc(const float* __restrict__ wq, const float* __restrict__ wk,
                          const float* __restrict__ wv, const float* __restrict__ wo) {
    int gtid = blockIdx.x * blockDim.x + threadIdx.x;
    int gstr = gridDim.x * blockDim.x;
    for (int j = gtid; j < CO * CO; j += gstr) {
        int o = j >> 6, c = j & 63;
        d_wot[c * CO + o] = wo[j];
    }
    for (int j = gtid; j < 192 * 128; j += gstr) {
        int m = j >> 7, k = j & 127;
        float v = 0.f;
        if (m < 64)        { if (k < 64)  v = wq[m * 64 + k]; }
        else if (m < 128)  { if (k < 64)  v = wk[(m - 64) * 64 + k]; }
        else               { if (k >= 64) v = wv[(m - 128) * 64 + (k - 64)]; }
        d_wqkvh[j] = __float2half(v);
    }
    for (int K = gtid; K < KTOT; K += gstr) {
        int ib = K >> 6, e = K & 63;
        int ci = K / 27, k = K - 27 * ci;
        int s  = ci - (64 * ib) / 27;        // 0..3
        ((uint8_t*)d_ktab64)[ib * 64 + e] =
            (uint8_t)((s << 6) | ((k & 3) << 4) | (k >> 2));
    }
}

// ---------------- raw-mma fp16 implicit-GEMM conv + BN + ELU ----------------
// grid (10, 128), 128 threads (4 warps). Double-buffered window/B/koff:
// iter+1 LDGs issue before iter's compute; STS lands after; ONE sync/iter.
#define W_OFF    0                    // 2 x 1152 floats = 9216
#define KOFF_OFF 9216                 // 2 x 64 ints = 512
#define CB_OFF   9728                 // 2 x 64*72 half = 18432
#define SM_CONV  28160                // Cs alias 64*68*4 = 17408 at 0

__global__ __launch_bounds__(128) void conv_mma(const float* __restrict__ x) {
    extern __shared__ char smem[];
    float*  Wb     = (float*)(smem + W_OFF);      // [buf][slot*288 + r*72 + a]
    int*    koff_s = (int*)(smem + KOFF_OFF);     // [buf][64]
    __half* Bsb    = (__half*)(smem + CB_OFF);    // [buf][k][o], ld 72
    float*  Cs     = (float*)smem;                // epilogue alias 64x68

    int tid = threadIdx.x, wid = tid >> 5, lid = tid & 31;
    int t0 = blockIdx.x * 64;
    int b  = blockIdx.y;
    int w0 = 4 * t0 - 13;

    const float* xb = x + (size_t)b * CIN * TIN;
    uint32_t Bbase = smem_u32(Bsb);
    int g  = lid >> 3, i5 = lid & 7;
    int lm_krow = i5 + (g & 1) * 8;
    int lm_ncol = (g >> 1) * 8;

    float acc[8][4];
    #pragma unroll
    for (int f = 0; f < 8; f++)
        #pragma unroll
        for (int j = 0; j < 4; j++) acc[f][j] = 0.f;

    int tA = wid * 16 + (lid >> 2);     // A row for this lane

    float wreg[9];
    int4  bload[4];
    int   kreg;

    auto load_regs = [&](int ibn) {
        int ci0 = (64 * ibn) / 27;
        #pragma unroll
        for (int i = 0; i < 9; i++) {
            int j2 = tid + i * 128;
            float v = 0.f;
            if (j2 < 1152) {
                int slot = j2 / 288, j = j2 - slot * 288;
                int ci = ci0 + slot, gp = w0 + j;
                if (j < 279 && ci < CIN && (unsigned)gp < (unsigned)TIN)
                    v = __ldg(xb + ci * TIN + gp);
            }
            wreg[i] = v;
        }
        const int4* bsrc = (const int4*)(d_wh + ibn * 4096);
        #pragma unroll
        for (int e = 0; e < 4; e++) bload[e] = __ldg(bsrc + tid + e * 128);
        kreg = (tid < 64) ? ((const uint8_t*)d_ktab64)[ibn * 64 + tid] : 0;
    };

    auto sts = [&](int buf) {
        float* W = Wb + buf * 1152;
        #pragma unroll
        for (int i = 0; i < 9; i++) {
            int j2 = tid + i * 128;
            if (j2 < 1152) {
                int slot = j2 / 288, j = j2 - slot * 288;
                W[slot * 288 + (j & 3) * 72 + (j >> 2)] = wreg[i];
            }
        }
        __half* Bs = Bsb + buf * 4608;
        #pragma unroll
        for (int e = 0; e < 4; e++) {
            int idx = tid + e * 128;
            int r = idx >> 3, sg = idx & 7;
            *(int4*)&Bs[r * 72 + sg * 8] = bload[e];
        }
        if (tid < 64)
            koff_s[buf * 64 + tid] =
                (kreg >> 6) * 288 + ((kreg >> 4) & 3) * 72 + (kreg & 15);
    };

    auto compute = [&](int buf) {
        const float* W  = Wb + buf * 1152;
        const int*   ko = koff_s + buf * 64;
        uint32_t Bb = Bbase + (uint32_t)(buf * 9216);
        #pragma unroll
        for (int kk = 0; kk < 4; kk++) {
            int kb0 = kk * 16 + (lid & 3) * 2;
            int o0 = ko[kb0], o1 = ko[kb0 + 1];
            int o2 = ko[kb0 + 8], o3 = ko[kb0 + 9];
            __half2 h;
            uint32_t a0, a1, a2, a3;
            h = __floats2half2_rn(W[o0 + tA],     W[o1 + tA]);     a0 = *(uint32_t*)&h;
            h = __floats2half2_rn(W[o0 + tA + 8], W[o1 + tA + 8]); a1 = *(uint32_t*)&h;
            h = __floats2half2_rn(W[o2 + tA],     W[o3 + tA]);     a2 = *(uint32_t*)&h;
            h = __floats2half2_rn(W[o2 + tA + 8], W[o3 + tA + 8]); a3 = *(uint32_t*)&h;

            #pragma unroll
            for (int np = 0; np < 4; np++) {
                uint32_t b0, b1, b2, b3;
                uint32_t baddr = Bb +
                    (uint32_t)(((kk * 16 + lm_krow) * 72 + np * 16 + lm_ncol) * 2);
                asm volatile(
                    "ldmatrix.sync.aligned.m8n8.x4.trans.shared.b16 "
                    "{%0,%1,%2,%3}, [%4];"
                    : "=r"(b0), "=r"(b1), "=r"(b2), "=r"(b3) : "r"(baddr));
                mma16816(acc[np * 2],     a0, a1, a2, a3, b0, b1);
                mma16816(acc[np * 2 + 1], a0, a1, a2, a3, b2, b3);
            }
        }
    };

    // ---- software pipeline: one sync per iteration ----
    load_regs(0);
    sts(0);
    __syncthreads();

    for (int ib = 0; ib < NKB2; ib++) {
        int buf = ib & 1;
        if (ib + 1 < NKB2) load_regs(ib + 1);   // LDGs fly under compute
        compute(buf);
        if (ib + 1 < NKB2) sts(buf ^ 1);        // data arrived by now
        __syncthreads();                         // publish buf^1; buf safe to refill
    }

    // accum -> Cs (aliases W/B; last sync above guards it)
    {
        int r = wid * 16 + (lid >> 2);
        int cb2 = (lid & 3) * 2;
        #pragma unroll
        for (int f = 0; f < 8; f++) {
            int c = f * 8 + cb2;
            Cs[r * 68 + c]           = acc[f][0];
            Cs[r * 68 + c + 1]       = acc[f][1];
            Cs[(r + 8) * 68 + c]     = acc[f][2];
            Cs[(r + 8) * 68 + c + 1] = acc[f][3];
        }
    }
    __syncthreads();

    #pragma unroll
    for (int it = 0; it < 32; it++) {
        int idx = it * 128 + tid;
        int o  = idx >> 6;
        int tl = idx & 63;
        int t  = t0 + tl;
        if (t < TOUT) {
            float v = Cs[tl * 68 + o] * __ldg(d_scale + o) + __ldg(d_shift + o);
            v = (v > 0.f) ? v : expm1f(v);
            d_y[((size_t)b * CO + o) * TOUT + t] = v;
        }
    }
}

// ---------------- qkv as one wmma GEMM: [192x128] x [128x64] ----------------
#define BLD  72
#define QB_OFF 0
#define QA_OFF 18432
#define QC_OFF 18432
#define SM_QKV (18432 + 52224)

__global__ __launch_bounds__(256) void qkv_gemm() {
    extern __shared__ char smem[];
    __half* Bh = (__half*)(smem + QB_OFF);
    __half* Ah = (__half*)(smem + QA_OFF);
    float*  Cs = (float*)(smem + QC_OFF);

    int t0  = blockIdx.x * 64;
    int b   = blockIdx.y;
    int tid = threadIdx.x;
    int wid = tid >> 5;
    int warp_m = wid & 3;
    int warp_n = wid >> 2;

    for (int j = tid; j < 4096; j += 256) {
        int c = j >> 6, tl = j & 63;
        int t = t0 + tl;
        float yv = (t < TOUT) ? d_y[((size_t)b * CO + c) * TOUT + t] : 0.f;
        Bh[c * BLD + tl]        = __float2half(yv > 0.f ? 1.f : 0.f);
        Bh[(64 + c) * BLD + tl] = __float2half(yv);
    }
    {
        const int4* asrc = (const int4*)d_wqkvh;
        #pragma unroll
        for (int e = 0; e < 12; e++) {
            int idx = tid + e * 256;
            int m = idx >> 4, seg = idx & 15;
            *(int4*)&Ah[m * 136 + seg * 8] = __ldg(asrc + idx);
        }
    }
    __syncthreads();

    wmma::fragment<wmma::accumulator, 16, 16, 16, float> acc[3][2];
    #pragma unroll
    for (int i = 0; i < 3; i++)
        #pragma unroll
        for (int j = 0; j < 2; j++) wmma::fill_fragment(acc[i][j], 0.f);

    #pragma unroll
    for (int kk = 0; kk < 8; kk++) {
        wmma::fragment<wmma::matrix_a, 16, 16, 16, __half, wmma::row_major> af[3];
        wmma::fragment<wmma::matrix_b, 16, 16, 16, __half, wmma::row_major> bf[2];
        #pragma unroll
        for (int i = 0; i < 3; i++)
            wmma::load_matrix_sync(af[i], Ah + (warp_m * 48 + i * 16) * 136 + kk * 16, 136);
        #pragma unroll
        for (int j = 0; j < 2; j++)
            wmma::load_matrix_sync(bf[j], Bh + (kk * 16) * BLD + warp_n * 32 + j * 16, BLD);
        #pragma unroll
        for (int i = 0; i < 3; i++)
            #pragma unroll
            for (int j = 0; j < 2; j++)
                wmma::mma_sync(acc[i][j], af[i], bf[j], acc[i][j]);
    }
    __syncthreads();

    #pragma unroll
    for (int i = 0; i < 3; i++)
        #pragma unroll
        for (int j = 0; j < 2; j++)
            wmma::store_matrix_sync(Cs + (warp_m * 48 + i * 16) * 68 + warp_n * 32 + j * 16,
                                    acc[i][j], 68, wmma::mem_row_major);
    __syncthreads();

    for (int j = tid; j < 4096; j += 256) {
        int tl = j >> 6, o = j & 63;
        int t = t0 + tl;
        if (t < TOUT) d_qh[((size_t)b * TOUT + t) * CO + o] = __float2half(Cs[o * 68 + tl]);
    }
    for (int j = tid; j < 4096; j += 256) {
        int o = j >> 6, tl = j & 63;
        int t = t0 + tl;
        if (t < TOUT) d_kh[((size_t)b * CO + o) * TOUT + t] = __float2half(Cs[(64 + o) * 68 + tl]);
    }
    for (int j = tid; j < 4096; j += 256) {
        int tl = j >> 6, o = j & 63;
        int t = t0 + tl;
        if (t < TOUT) d_vh[((size_t)b * TOUT + t) * CO + o] = __float2half(Cs[(128 + o) * 68 + tl]);
    }
}

// ---------------- wmma attention (fixed-shift softmax) + wo + residual ----------------
#define QH_OFF   0
#define KH_OFF   9216
#define VH_OFF   18432
#define PH_OFF   27648
#define SF_OFF   36864
#define RL_OFF   54272
#define SM_ATT   55296

__global__ __launch_bounds__(256) void attn_wmma(float* __restrict__ out) {
    extern __shared__ char smem[];
    __half* Qh = (__half*)(smem + QH_OFF);
    __half* Kh = (__half*)(smem + KH_OFF);
    __half* Vh = (__half*)(smem + VH_OFF);
    __half* Ph = (__half*)(smem + PH_OFF);
    float*  Sf = (float*)(smem + SF_OFF);
    float*  redl = (float*)(smem + RL_OFF);
    float*  wot_s = (float*)(smem + QH_OFF);

    int t0   = blockIdx.x * 64;
    int b    = blockIdx.y;
    int tid  = threadIdx.x;
    int wid  = tid >> 5;
    int q    = tid & 63;
    int part = tid >> 6;
    int cb   = part * 16;
    int warp_m = wid & 3;
    int warp_n = wid >> 2;

    for (int j = tid; j < 4096; j += 256) {
        int tl = j >> 6, c = j & 63;
        int t = t0 + tl;
        Qh[tl * 72 + c] = (t < TOUT) ? d_qh[((size_t)b * TOUT + t) * CO + c]
                                     : __float2half(0.f);
    }

    wmma::fragment<wmma::accumulator, 16, 16, 16, float> ctx[2];
    #pragma unroll
    for (int j = 0; j < 2; j++) wmma::fill_fragment(ctx[j], 0.f);

    float l = 0.f;

    for (int stile = 0; stile < 10; stile++) {
        int s0 = stile * 64;
        __syncthreads();

        for (int j = tid; j < 4096; j += 256) {
            int c = j >> 6, sl = j & 63;
            int s = s0 + sl;
            Kh[c * 72 + sl] = (s < TOUT) ? d_kh[((size_t)b * CO + c) * TOUT + s]
                                         : __float2half(0.f);
        }
        for (int j = tid; j < 4096; j += 256) {
            int sl = j >> 6, c = j & 63;
            int s = s0 + sl;
            Vh[sl * 72 + c] = (s < TOUT) ? d_vh[((size_t)b * TOUT + s) * CO + c]
                                         : __float2half(0.f);
        }
        __syncthreads();

        {
            wmma::fragment<wmma::accumulator, 16, 16, 16, float> sacc[2];
            #pragma unroll
            for (int j = 0; j < 2; j++) wmma::fill_fragment(sacc[j], 0.f);
            #pragma unroll
            for (int kk = 0; kk < 4; kk++) {
                wmma::fragment<wmma::matrix_a, 16, 16, 16, __half, wmma::row_major> af;
                wmma::fragment<wmma::matrix_b, 16, 16, 16, __half, wmma::row_major> bf[2];
                wmma::load_matrix_sync(af, Qh + (warp_m * 16) * 72 + kk * 16, 72);
                #pragma unroll
                for (int j = 0; j < 2; j++)
                    wmma::load_matrix_sync(bf[j], Kh + (kk * 16) * 72 + warp_n * 32 + j * 16, 72);
                #pragma unroll
                for (int j = 0; j < 2; j++)
                    wmma::mma_sync(sacc[j], af, bf[j], sacc[j]);
            }
            #pragma unroll
            for (int j = 0; j < 2; j++)
                wmma::store_matrix_sync(Sf + (warp_m * 16) * 68 + warp_n * 32 + j * 16,
                                        sacc[j], 68, wmma::mem_row_major);
        }
        __syncthreads();

        {
            float lp = 0.f;
            const float4* sr = (const float4*)&Sf[q * 68 + cb];
            float4 s4[4] = { sr[0], sr[1], sr[2], sr[3] };
            float sv[16] = { s4[0].x, s4[0].y, s4[0].z, s4[0].w,
                             s4[1].x, s4[1].y, s4[1].z, s4[1].w,
                             s4[2].x, s4[2].y, s4[2].z, s4[2].w,
                             s4[3].x, s4[3].y, s4[3].z, s4[3].w };
            #pragma unroll
            for (int i = 0; i < 16; i++) {
                int sg = s0 + cb + i;
                float p = (sg < TOUT) ? __expf(sv[i] * 0.125f) : 0.f;
                Ph[q * 72 + cb + i] = __float2half(p);
                lp += p;
            }
            redl[part * 64 + q] = lp;
        }
        __syncthreads();

        l += redl[q] + redl[64 + q] + redl[128 + q] + redl[192 + q];

        #pragma unroll
        for (int kk = 0; kk < 4; kk++) {
            wmma::fragment<wmma::matrix_a, 16, 16, 16, __half, wmma::row_major> af;
            wmma::fragment<wmma::matrix_b, 16, 16, 16, __half, wmma::row_major> bf[2];
            wmma::load_matrix_sync(af, Ph + (warp_m * 16) * 72 + kk * 16, 72);
            #pragma unroll
            for (int j = 0; j < 2; j++)
                wmma::load_matrix_sync(bf[j], Vh + (kk * 16) * 72 + warp_n * 32 + j * 16, 72);
            #pragma unroll
            for (int j = 0; j < 2; j++)
                wmma::mma_sync(ctx[j], af, bf[j], ctx[j]);
        }
    }

    __syncthreads();
    #pragma unroll
    for (int j = 0; j < 2; j++)
        wmma::store_matrix_sync(Sf + (warp_m * 16) * 68 + warp_n * 32 + j * 16,
                                ctx[j], 68, wmma::mem_row_major);
    for (int j = tid; j < 4096; j += 256) wot_s[j] = d_wot[j];
    __syncthreads();

    float invl = 1.f / l;
    float ob[16];
    #pragma unroll
    for (int i = 0; i < 16; i++) ob[i] = 0.f;
    for (int c = 0; c < CO; c++) {
        float cv = Sf[q * 68 + c] * invl;
        const float4* wr = (const float4*)&wot_s[c * 64 + cb];
        float4 w0 = wr[0], w1 = wr[1], w2 = wr[2], w3 = wr[3];
        ob[0]  = fmaf(cv, w0.x, ob[0]);  ob[1]  = fmaf(cv, w0.y, ob[1]);
        ob[2]  = fmaf(cv, w0.z, ob[2]);  ob[3]  = fmaf(cv, w0.w, ob[3]);
        ob[4]  = fmaf(cv, w1.x, ob[4]);  ob[5]  = fmaf(cv, w1.y, ob[5]);
        ob[6]  = fmaf(cv, w1.z, ob[6]);  ob[7]  = fmaf(cv, w1.w, ob[7]);
        ob[8]  = fmaf(cv, w2.x, ob[8]);  ob[9]  = fmaf(cv, w2.y, ob[9]);
        ob[10] = fmaf(cv, w2.z, ob[10]); ob[11] = fmaf(cv, w2.w, ob[11]);
        ob[12] = fmaf(cv, w3.x, ob[12]); ob[13] = fmaf(cv, w3.y, ob[13]);
        ob[14] = fmaf(cv, w3.z, ob[14]); ob[15] = fmaf(cv, w3.w, ob[15]);
    }

    int t = t0 + q;
    if (t < TOUT) {
        #pragma unroll
        for (int i = 0; i < 16; i++) {
            int o = cb + i;
            out[((size_t)b * CO + o) * TOUT + t] =
                d_y[((size_t)b * CO + o) * TOUT + t] + ob[i];
        }
    }
}

// ---------------- launch ----------------
extern "C" void kernel_launch(void* const* d_in, const int* in_sizes, int n_in,
                              void* d_out, int out_size) {
    const float* x      = (const float*)d_in[0];
    const float* conv_w = (const float*)d_in[1];
    const float* conv_b = (const float*)d_in[2];
    const float* gamma  = (const float*)d_in[3];
    const float* beta   = (const float*)d_in[4];
    const float* mean   = (const float*)d_in[5];
    const float* var    = (const float*)d_in[6];
    const float* wq     = (const float*)d_in[7];
    const float* wk     = (const float*)d_in[8];
    const float* wv     = (const float*)d_in[9];
    const float* wo     = (const float*)d_in[10];
    float* out = (float*)d_out;

    prep_weights<<<64, 256>>>(conv_w, conv_b, gamma, beta, mean, var);
    prep_misc<<<16, 256>>>(wq, wk, wv, wo);

    cudaFuncSetAttribute(conv_mma, cudaFuncAttributeMaxDynamicSharedMemorySize, SM_CONV);
    conv_mma<<<dim3(10, NB), 128, SM_CONV>>>(x);

    cudaFuncSetAttribute(qkv_gemm, cudaFuncAttributeMaxDynamicSharedMemorySize, SM_QKV);
    qkv_gemm<<<dim3(10, NB), 256, SM_QKV>>>();

    cudaFuncSetAttribute(attn_wmma, cudaFuncAttributeMaxDynamicSharedMemorySize, SM_ATT);
    attn_wmma<<<dim3(10, NB), 256, SM_ATT>>>(out);
}